// round 1
// baseline (speedup 1.0000x reference)
#include <cuda_runtime.h>
#include <math.h>

#define BB 2
#define TT 2048
#define DIMM 1024
#define HH 16
#define DHH 64
#define M_TOT (BB*TT)        /* 4096 */

// Scratch (static device globals; allocation is forbidden)
__device__ float g_q[(size_t)BB*HH*TT*DHH];
__device__ float g_k[(size_t)BB*HH*TT*DHH];
__device__ float g_v[(size_t)BB*HH*TT*DHH];
__device__ float g_y[(size_t)BB*HH*TT*DHH];

// ---------------------------------------------------------------------------
// Tiled fp32 GEMM, 128x128 block tile, BK=8, 256 threads, 8x8 per thread.
// MODE 0: C = x @ W_qkv + b_qkv, scatter into g_q/g_k/g_v as [B,H,T,DH]
// MODE 1: C = y(gathered from g_y [B,H,T,DH]) @ W_out + b_out -> out [M,1024]
// ---------------------------------------------------------------------------
template <int MODE>
__global__ __launch_bounds__(256, 2) void gemm_kernel(
    const float* __restrict__ A, const float* __restrict__ Bm,
    const float* __restrict__ bias, float* __restrict__ out, int NB)
{
    __shared__ float As[8][132];
    __shared__ float Bs[8][128];

    const int tid = threadIdx.x;
    const int tx = tid & 15;
    const int ty = tid >> 4;
    const int m0 = blockIdx.y * 128;
    const int n0 = blockIdx.x * 128;
    const int K = 1024;

    // A-load mapping: each thread loads one float4 of A per chunk
    const int am  = tid >> 1;          // 0..127 (row within tile)
    const int akq = (tid & 1) * 4;     // 0 or 4 (k offset)
    // B-load mapping
    const int bk = tid >> 5;           // 0..7
    const int bn = (tid & 31) * 4;     // 0..124

    float acc[8][8];
#pragma unroll
    for (int i = 0; i < 8; i++)
#pragma unroll
        for (int j = 0; j < 8; j++) acc[i][j] = 0.f;

    for (int k0 = 0; k0 < K; k0 += 8) {
        float4 a4;
        if (MODE == 0) {
            a4 = *(const float4*)&A[(size_t)(m0 + am) * K + k0 + akq];
        } else {
            const int m = m0 + am;
            const int b = m >> 11, t = m & (TT - 1);
            const int kk = k0 + akq;
            const int h = kk >> 6, d = kk & 63;
            a4 = *(const float4*)&g_y[(((size_t)b * HH + h) * TT + t) * DHH + d];
        }
        As[akq + 0][am] = a4.x;
        As[akq + 1][am] = a4.y;
        As[akq + 2][am] = a4.z;
        As[akq + 3][am] = a4.w;
        *(float4*)&Bs[bk][bn] =
            *(const float4*)&Bm[(size_t)(k0 + bk) * NB + n0 + bn];
        __syncthreads();

#pragma unroll
        for (int k = 0; k < 8; k++) {
            float4 a0 = *(const float4*)&As[k][ty * 4];
            float4 a1 = *(const float4*)&As[k][64 + ty * 4];
            float4 b0 = *(const float4*)&Bs[k][tx * 4];
            float4 b1 = *(const float4*)&Bs[k][64 + tx * 4];
            float af[8] = {a0.x, a0.y, a0.z, a0.w, a1.x, a1.y, a1.z, a1.w};
            float bf[8] = {b0.x, b0.y, b0.z, b0.w, b1.x, b1.y, b1.z, b1.w};
#pragma unroll
            for (int i = 0; i < 8; i++)
#pragma unroll
                for (int j = 0; j < 8; j++)
                    acc[i][j] = fmaf(af[i], bf[j], acc[i][j]);
        }
        __syncthreads();
    }

    // Epilogue
#pragma unroll
    for (int i = 0; i < 8; i++) {
        const int row = (i < 4) ? (ty * 4 + i) : (64 + ty * 4 + i - 4);
        const int m = m0 + row;
#pragma unroll
        for (int g = 0; g < 2; g++) {
            const int n = n0 + g * 64 + tx * 4;
            float4 bv = *(const float4*)&bias[n];
            float4 o;
            o.x = acc[i][g * 4 + 0] + bv.x;
            o.y = acc[i][g * 4 + 1] + bv.y;
            o.z = acc[i][g * 4 + 2] + bv.z;
            o.w = acc[i][g * 4 + 3] + bv.w;
            if (MODE == 0) {
                const int which = n >> 10;
                const int r = n & 1023;
                const int h = r >> 6, d = r & 63;
                const int b = m >> 11, t = m & (TT - 1);
                float* dst = (which == 0) ? g_q : (which == 1) ? g_k : g_v;
                *(float4*)&dst[(((size_t)b * HH + h) * TT + t) * DHH + d] = o;
            } else {
                *(float4*)&out[(size_t)m * DIMM + n] = o;
            }
        }
    }
}

// ---------------------------------------------------------------------------
// RoPE applied in place to g_q, g_k ([B*H, T, DH] layout).
// Matches the reference's fp32 chain: inv rounded to f32, angle in f32,
// sin/cos evaluated accurately (double) on the f32 angle.
// ---------------------------------------------------------------------------
__global__ void rope_kernel()
{
    const int idx = blockIdx.x * blockDim.x + threadIdx.x;   // 2^21 threads
    const int d  = idx & 31;
    const int t  = (idx >> 5) & (TT - 1);
    const int bh = idx >> 16;

    const float invf = (float)exp(-(double)d * (log(10000.0) / 32.0));
    const float ang = (float)t * invf;
    double sd, cd;
    sincos((double)ang, &sd, &cd);
    const float cf = (float)cd, sf = (float)sd;

    const size_t base = ((size_t)bh * TT + t) * DHH;
    const float qa = g_q[base + d], qb = g_q[base + 32 + d];
    g_q[base + d]      = qa * cf - qb * sf;
    g_q[base + 32 + d] = qa * sf + qb * cf;
    const float ka = g_k[base + d], kb = g_k[base + 32 + d];
    g_k[base + d]      = ka * cf - kb * sf;
    g_k[base + 32 + d] = ka * sf + kb * cf;
}

// ---------------------------------------------------------------------------
// Flash attention (fp32, causal). One block per (q-tile of 64 rows, b*h).
// 256 threads: thread (tx,ty) owns rows ty*4+i, cols tx+16*j.
// Conflict-free smem: row stride 65 floats.
// ---------------------------------------------------------------------------
#define SMEM_ATTN (4 * 64 * 65 * 4)

__global__ __launch_bounds__(256) void attn_kernel()
{
    extern __shared__ float sm[];
    float* Qs = sm;                  // [64][65]
    float* Ks = sm + 64 * 65;
    float* Vs = sm + 2 * 64 * 65;
    float* Ps = sm + 3 * 64 * 65;

    const int qt = blockIdx.x;       // 0..31
    const int bh = blockIdx.y;       // 0..31
    const int tid = threadIdx.x;
    const int tx = tid & 15;
    const int ty = tid >> 4;

    const float* Qg = g_q + ((size_t)bh * TT + qt * 64) * DHH;
    const float* Kg = g_k + (size_t)bh * TT * DHH;
    const float* Vg = g_v + (size_t)bh * TT * DHH;

    // Load Q tile (64x64) into smem
#pragma unroll
    for (int g = 0; g < 4; g++) {
        const int e = g * 256 + tid;
        const int r = e >> 4, dq = (e & 15) * 4;
        float4 v4 = *(const float4*)&Qg[r * DHH + dq];
        Qs[r * 65 + dq + 0] = v4.x;
        Qs[r * 65 + dq + 1] = v4.y;
        Qs[r * 65 + dq + 2] = v4.z;
        Qs[r * 65 + dq + 3] = v4.w;
    }

    float m_prev[4], l_acc[4], acc[4][4];
#pragma unroll
    for (int i = 0; i < 4; i++) {
        m_prev[i] = -INFINITY;
        l_acc[i] = 0.f;
#pragma unroll
        for (int j = 0; j < 4; j++) acc[i][j] = 0.f;
    }

    const int qrow0 = qt * 64 + ty * 4;

    for (int kt = 0; kt <= qt; kt++) {
        __syncthreads();  // previous iteration's readers of Ks/Vs/Ps are done
        const float* Kt = Kg + (size_t)kt * 64 * DHH;
        const float* Vt = Vg + (size_t)kt * 64 * DHH;
#pragma unroll
        for (int g = 0; g < 4; g++) {
            const int e = g * 256 + tid;
            const int r = e >> 4, dq = (e & 15) * 4;
            float4 kv = *(const float4*)&Kt[r * DHH + dq];
            Ks[r * 65 + dq + 0] = kv.x;
            Ks[r * 65 + dq + 1] = kv.y;
            Ks[r * 65 + dq + 2] = kv.z;
            Ks[r * 65 + dq + 3] = kv.w;
            float4 vv = *(const float4*)&Vt[r * DHH + dq];
            Vs[r * 65 + dq + 0] = vv.x;
            Vs[r * 65 + dq + 1] = vv.y;
            Vs[r * 65 + dq + 2] = vv.z;
            Vs[r * 65 + dq + 3] = vv.w;
        }
        __syncthreads();

        // S = Q K^T for this tile
        float s[4][4];
#pragma unroll
        for (int i = 0; i < 4; i++)
#pragma unroll
            for (int j = 0; j < 4; j++) s[i][j] = 0.f;

#pragma unroll 8
        for (int d = 0; d < 64; d++) {
            float a0 = Qs[(ty * 4 + 0) * 65 + d];
            float a1 = Qs[(ty * 4 + 1) * 65 + d];
            float a2 = Qs[(ty * 4 + 2) * 65 + d];
            float a3 = Qs[(ty * 4 + 3) * 65 + d];
            float b0 = Ks[(tx + 0)  * 65 + d];
            float b1 = Ks[(tx + 16) * 65 + d];
            float b2 = Ks[(tx + 32) * 65 + d];
            float b3 = Ks[(tx + 48) * 65 + d];
            s[0][0] = fmaf(a0, b0, s[0][0]); s[0][1] = fmaf(a0, b1, s[0][1]);
            s[0][2] = fmaf(a0, b2, s[0][2]); s[0][3] = fmaf(a0, b3, s[0][3]);
            s[1][0] = fmaf(a1, b0, s[1][0]); s[1][1] = fmaf(a1, b1, s[1][1]);
            s[1][2] = fmaf(a1, b2, s[1][2]); s[1][3] = fmaf(a1, b3, s[1][3]);
            s[2][0] = fmaf(a2, b0, s[2][0]); s[2][1] = fmaf(a2, b1, s[2][1]);
            s[2][2] = fmaf(a2, b2, s[2][2]); s[2][3] = fmaf(a2, b3, s[2][3]);
            s[3][0] = fmaf(a3, b0, s[3][0]); s[3][1] = fmaf(a3, b1, s[3][1]);
            s[3][2] = fmaf(a3, b2, s[3][2]); s[3][3] = fmaf(a3, b3, s[3][3]);
        }

        // scale + causal mask
#pragma unroll
        for (int i = 0; i < 4; i++)
#pragma unroll
            for (int j = 0; j < 4; j++) {
                const int kc = kt * 64 + tx + 16 * j;
                s[i][j] = (kc <= qrow0 + i) ? s[i][j] * 0.125f : -INFINITY;
            }

        // online softmax update
        float m_new[4], corr[4], p[4][4];
#pragma unroll
        for (int i = 0; i < 4; i++) {
            float tm = fmaxf(fmaxf(s[i][0], s[i][1]), fmaxf(s[i][2], s[i][3]));
#pragma unroll
            for (int off = 8; off > 0; off >>= 1)
                tm = fmaxf(tm, __shfl_xor_sync(0xffffffffu, tm, off, 16));
            m_new[i] = fmaxf(m_prev[i], tm);
            corr[i] = expf(m_prev[i] - m_new[i]);
        }
#pragma unroll
        for (int i = 0; i < 4; i++) {
            float rs = 0.f;
#pragma unroll
            for (int j = 0; j < 4; j++) {
                p[i][j] = expf(s[i][j] - m_new[i]);
                rs += p[i][j];
            }
#pragma unroll
            for (int off = 8; off > 0; off >>= 1)
                rs += __shfl_xor_sync(0xffffffffu, rs, off, 16);
            l_acc[i] = l_acc[i] * corr[i] + rs;
#pragma unroll
            for (int j = 0; j < 4; j++) acc[i][j] *= corr[i];
        }

        // share P through smem
#pragma unroll
        for (int i = 0; i < 4; i++)
#pragma unroll
            for (int j = 0; j < 4; j++)
                Ps[(ty * 4 + i) * 65 + tx + 16 * j] = p[i][j];
        __syncthreads();

        // O += P V
#pragma unroll 8
        for (int k2 = 0; k2 < 64; k2++) {
            float p0 = Ps[(ty * 4 + 0) * 65 + k2];
            float p1 = Ps[(ty * 4 + 1) * 65 + k2];
            float p2 = Ps[(ty * 4 + 2) * 65 + k2];
            float p3 = Ps[(ty * 4 + 3) * 65 + k2];
            float v0 = Vs[k2 * 65 + tx + 0];
            float v1 = Vs[k2 * 65 + tx + 16];
            float v2 = Vs[k2 * 65 + tx + 32];
            float v3 = Vs[k2 * 65 + tx + 48];
            acc[0][0] = fmaf(p0, v0, acc[0][0]); acc[0][1] = fmaf(p0, v1, acc[0][1]);
            acc[0][2] = fmaf(p0, v2, acc[0][2]); acc[0][3] = fmaf(p0, v3, acc[0][3]);
            acc[1][0] = fmaf(p1, v0, acc[1][0]); acc[1][1] = fmaf(p1, v1, acc[1][1]);
            acc[1][2] = fmaf(p1, v2, acc[1][2]); acc[1][3] = fmaf(p1, v3, acc[1][3]);
            acc[2][0] = fmaf(p2, v0, acc[2][0]); acc[2][1] = fmaf(p2, v1, acc[2][1]);
            acc[2][2] = fmaf(p2, v2, acc[2][2]); acc[2][3] = fmaf(p2, v3, acc[2][3]);
            acc[3][0] = fmaf(p3, v0, acc[3][0]); acc[3][1] = fmaf(p3, v1, acc[3][1]);
            acc[3][2] = fmaf(p3, v2, acc[3][2]); acc[3][3] = fmaf(p3, v3, acc[3][3]);
        }
#pragma unroll
        for (int i = 0; i < 4; i++) m_prev[i] = m_new[i];
    }

    // Write O (normalized) to g_y
    float* Yg = g_y + ((size_t)bh * TT + qt * 64) * DHH;
#pragma unroll
    for (int i = 0; i < 4; i++) {
        const float inv_l = 1.f / l_acc[i];
#pragma unroll
        for (int j = 0; j < 4; j++)
            Yg[(ty * 4 + i) * DHH + tx + 16 * j] = acc[i][j] * inv_l;
    }
}

// ---------------------------------------------------------------------------
extern "C" void kernel_launch(void* const* d_in, const int* in_sizes, int n_in,
                              void* d_out, int out_size)
{
    (void)in_sizes; (void)n_in; (void)out_size;
    const float* x     = (const float*)d_in[0];
    // d_in[1] is the causal mask (int32) — causality is implemented directly.
    const float* W_qkv = (const float*)d_in[2];
    const float* b_qkv = (const float*)d_in[3];
    const float* W_out = (const float*)d_in[4];
    const float* b_out = (const float*)d_in[5];
    float* out = (float*)d_out;

    cudaFuncSetAttribute(attn_kernel,
                         cudaFuncAttributeMaxDynamicSharedMemorySize, SMEM_ATTN);

    // 1) QKV projection + scatter to [B,H,T,DH]
    gemm_kernel<0><<<dim3(3072 / 128, M_TOT / 128), 256>>>(x, W_qkv, b_qkv,
                                                           nullptr, 3072);
    // 2) RoPE in place on q, k
    rope_kernel<<<(BB * HH * TT * 32) / 256, 256>>>();
    // 3) causal flash attention
    attn_kernel<<<dim3(TT / 64, BB * HH), 256, SMEM_ATTN>>>();
    // 4) output projection
    gemm_kernel<1><<<dim3(DIMM / 128, M_TOT / 128), 256>>>(nullptr, W_out,
                                                           b_out, out, 1024);
}

// round 3
// speedup vs baseline: 1.4103x; 1.4103x over previous
#include <cuda_runtime.h>
#include <math.h>
#include <stdint.h>

#define BB 2
#define TT 2048
#define DIMM 1024
#define HH 16
#define DHH 64
#define M_TOT (BB*TT)        /* 4096 */

// Scratch (static device globals; allocation is forbidden)
__device__ float g_q[(size_t)BB*HH*TT*DHH];
__device__ float g_k[(size_t)BB*HH*TT*DHH];
__device__ float g_v[(size_t)BB*HH*TT*DHH];
__device__ float g_y[(size_t)BB*HH*TT*DHH];
__device__ float g_wtq[(size_t)3072*1024];   // W_qkv^T  [n][k]
__device__ float g_wto[(size_t)1024*1024];   // W_out^T  [n][k]

// ---------------------------------------------------------------------------
// Helpers: legacy mma.sync tf32 path (works at compute_103 target; tcgen05
// requires the sm_103a feature target which this harness does not emit).
// ---------------------------------------------------------------------------
__device__ __forceinline__ uint32_t smem_u32(const void* p) {
    uint32_t a;
    asm("{ .reg .u64 t; cvta.to.shared.u64 t, %1; cvt.u32.u64 %0, t; }"
        : "=r"(a) : "l"(p));
    return a;
}
__device__ __forceinline__ uint32_t cvt_tf32(float f) {
    uint32_t u;
    asm("cvt.rna.tf32.f32 %0, %1;" : "=r"(u) : "f"(f));
    return u;
}
#define CP16(sa, gp) \
    asm volatile("cp.async.cg.shared.global [%0], [%1], 16;" :: "r"(sa), "l"(gp))
#define CP_COMMIT() asm volatile("cp.async.commit_group;" ::: "memory")
#define CP_WAIT1()  asm volatile("cp.async.wait_group 1;" ::: "memory")
#define CP_WAIT0()  asm volatile("cp.async.wait_group 0;" ::: "memory")

__device__ __forceinline__ void mma_tf32(float* c, const uint32_t* a,
                                         const uint32_t* b) {
    asm volatile(
        "mma.sync.aligned.m16n8k8.row.col.f32.tf32.tf32.f32 "
        "{%0,%1,%2,%3}, {%4,%5,%6,%7}, {%8,%9}, {%0,%1,%2,%3};"
        : "+f"(c[0]), "+f"(c[1]), "+f"(c[2]), "+f"(c[3])
        : "r"(a[0]), "r"(a[1]), "r"(a[2]), "r"(a[3]), "r"(b[0]), "r"(b[1]));
}

// ---------------------------------------------------------------------------
// Weight transpose: src [1024][C] -> dst [C][1024]  (K-major for mma frags)
// ---------------------------------------------------------------------------
__global__ void transpose_kernel(const float* __restrict__ src,
                                 float* __restrict__ dst, int C)
{
    __shared__ float t[32][33];
    const int c0 = blockIdx.x * 32, r0 = blockIdx.y * 32;
    for (int i = threadIdx.y; i < 32; i += 8)
        t[i][threadIdx.x] = src[(size_t)(r0 + i) * C + c0 + threadIdx.x];
    __syncthreads();
    for (int i = threadIdx.y; i < 32; i += 8)
        dst[(size_t)(c0 + i) * 1024 + r0 + threadIdx.x] = t[threadIdx.x][i];
}

// ---------------------------------------------------------------------------
// mma.sync tf32 GEMM: CTA tile 128x128, BK=32, 8 warps (2x4), warp 64x32.
// A [m][k] row-major; Bt [n][k] K-major. Double-buffered cp.async SMEM.
// MODE 0: C = x @ W_qkv^T' + b_qkv -> scatter g_q/g_k/g_v [B,H,T,DH]
// MODE 1: C = y(gather [B,H,T,DH]) @ W_out^T' + b_out -> out [M,1024]
// ---------------------------------------------------------------------------
#define PAD 36
#define ATILE (128 * PAD * 4)          /* 18432 B */
#define STAGE (2 * ATILE)              /* A + B per stage */
#define GEMM_SMEM (2 * STAGE)          /* 73728 B */

template <int MODE>
__global__ __launch_bounds__(256) void gemm_mma(
    const float* __restrict__ A, const float* __restrict__ Bt,
    const float* __restrict__ bias, float* __restrict__ out)
{
    extern __shared__ char smem[];
    const uint32_t sb = smem_u32(smem);
    const int tid = threadIdx.x;
    const int wid = tid >> 5;
    const int lane = tid & 31;
    const int gid = lane >> 2;          // 0..7
    const int tg = lane & 3;            // 0..3
    const int mb = (wid >> 2) * 64;     // warp m offset (0/64)
    const int nb = (wid & 3) * 32;      // warp n offset (0..96)
    const int m0 = blockIdx.y * 128;
    const int n0 = blockIdx.x * 128;

    float acc[4][4][4];
#pragma unroll
    for (int mf = 0; mf < 4; mf++)
#pragma unroll
        for (int nf = 0; nf < 4; nf++)
#pragma unroll
            for (int i = 0; i < 4; i++) acc[mf][nf][i] = 0.f;

    const int r = tid >> 3;             // 0..31 per pass? no: 0..31? tid/8 -> 0..31
    // Each thread copies 4 float4 for A and 4 for B per tile (1024 each).

    auto issue_tile = [&](int c) {
        const int p = c & 1;
        const int k0 = c * 32;
        const uint32_t aBase = sb + p * STAGE;
        const uint32_t bBase = aBase + ATILE;
#pragma unroll
        for (int i = 0; i < 4; i++) {
            const int e = tid + 256 * i;
            const int rr = e >> 3, q = e & 7;
            const float* gp;
            if (MODE == 0) {
                gp = &A[(size_t)(m0 + rr) * 1024 + k0 + q * 4];
            } else {
                const int m = m0 + rr, b = m >> 11, t = m & (TT - 1);
                const int kk = k0 + q * 4, h = kk >> 6, d = kk & 63;
                gp = &g_y[(((size_t)b * HH + h) * TT + t) * DHH + d];
            }
            CP16(aBase + (uint32_t)(rr * PAD + q * 4) * 4, gp);
        }
#pragma unroll
        for (int i = 0; i < 4; i++) {
            const int e = tid + 256 * i;
            const int rr = e >> 3, q = e & 7;
            const float* gp = &Bt[(size_t)(n0 + rr) * 1024 + k0 + q * 4];
            CP16(bBase + (uint32_t)(rr * PAD + q * 4) * 4, gp);
        }
        CP_COMMIT();
    };

    issue_tile(0);
    for (int c = 0; c < 32; c++) {
        if (c + 1 < 32) { issue_tile(c + 1); CP_WAIT1(); }
        else            { CP_WAIT0(); }
        __syncthreads();

        const int p = c & 1;
        const float* As = (const float*)(smem + p * STAGE);
        const float* Bs = (const float*)(smem + p * STAGE + ATILE);
#pragma unroll
        for (int ks = 0; ks < 4; ks++) {
            const int kk = ks * 8;
            uint32_t af[4][4], bf[4][2];
#pragma unroll
            for (int mf = 0; mf < 4; mf++) {
                const float* ap = As + (mb + mf * 16 + gid) * PAD + kk + tg;
                af[mf][0] = cvt_tf32(ap[0]);
                af[mf][1] = cvt_tf32(ap[8 * PAD]);
                af[mf][2] = cvt_tf32(ap[4]);
                af[mf][3] = cvt_tf32(ap[8 * PAD + 4]);
            }
#pragma unroll
            for (int nf = 0; nf < 4; nf++) {
                const float* bp = Bs + (nb + nf * 8 + gid) * PAD + kk + tg;
                bf[nf][0] = cvt_tf32(bp[0]);
                bf[nf][1] = cvt_tf32(bp[4]);
            }
#pragma unroll
            for (int mf = 0; mf < 4; mf++)
#pragma unroll
                for (int nf = 0; nf < 4; nf++)
                    mma_tf32(acc[mf][nf], af[mf], bf[nf]);
        }
        __syncthreads();
    }

    // Epilogue: bias + store (float2 per fragment half)
#pragma unroll
    for (int mf = 0; mf < 4; mf++) {
        const int r0 = m0 + mb + mf * 16 + gid;
#pragma unroll
        for (int nf = 0; nf < 4; nf++) {
            const int n = n0 + nb + nf * 8 + tg * 2;
            const float bx = bias[n], by = bias[n + 1];
            float2 v0 = make_float2(acc[mf][nf][0] + bx, acc[mf][nf][1] + by);
            float2 v1 = make_float2(acc[mf][nf][2] + bx, acc[mf][nf][3] + by);
            if (MODE == 0) {
                const int which = n >> 10;
                const int rr = n & 1023;
                const int h = rr >> 6, d = rr & 63;
                float* dst = (which == 0) ? g_q : (which == 1) ? g_k : g_v;
                {
                    const int b = r0 >> 11, t = r0 & (TT - 1);
                    *(float2*)&dst[(((size_t)b * HH + h) * TT + t) * DHH + d] = v0;
                }
                {
                    const int m1 = r0 + 8;
                    const int b = m1 >> 11, t = m1 & (TT - 1);
                    *(float2*)&dst[(((size_t)b * HH + h) * TT + t) * DHH + d] = v1;
                }
            } else {
                *(float2*)&out[(size_t)r0 * DIMM + n] = v0;
                *(float2*)&out[(size_t)(r0 + 8) * DIMM + n] = v1;
            }
        }
    }
}

// ---------------------------------------------------------------------------
// RoPE (matches reference fp32 chain)
// ---------------------------------------------------------------------------
__global__ void rope_kernel()
{
    const int idx = blockIdx.x * blockDim.x + threadIdx.x;
    const int d  = idx & 31;
    const int t  = (idx >> 5) & (TT - 1);
    const int bh = idx >> 16;

    const float invf = (float)exp(-(double)d * (log(10000.0) / 32.0));
    const float ang = (float)t * invf;
    double sd, cd;
    sincos((double)ang, &sd, &cd);
    const float cf = (float)cd, sf = (float)sd;

    const size_t base = ((size_t)bh * TT + t) * DHH;
    const float qa = g_q[base + d], qb = g_q[base + 32 + d];
    g_q[base + d]      = qa * cf - qb * sf;
    g_q[base + 32 + d] = qa * sf + qb * cf;
    const float ka = g_k[base + d], kb = g_k[base + 32 + d];
    g_k[base + d]      = ka * cf - kb * sf;
    g_k[base + 32 + d] = ka * sf + kb * cf;
}

// ---------------------------------------------------------------------------
// Flash attention (fp32 SIMT, unchanged from passing round-1 kernel)
// ---------------------------------------------------------------------------
#define SMEM_ATTN (4 * 64 * 65 * 4)

__global__ __launch_bounds__(256) void attn_kernel()
{
    extern __shared__ float sm[];
    float* Qs = sm;
    float* Ks = sm + 64 * 65;
    float* Vs = sm + 2 * 64 * 65;
    float* Ps = sm + 3 * 64 * 65;

    const int qt = blockIdx.x;
    const int bh = blockIdx.y;
    const int tid = threadIdx.x;
    const int tx = tid & 15;
    const int ty = tid >> 4;

    const float* Qg = g_q + ((size_t)bh * TT + qt * 64) * DHH;
    const float* Kg = g_k + (size_t)bh * TT * DHH;
    const float* Vg = g_v + (size_t)bh * TT * DHH;

#pragma unroll
    for (int g = 0; g < 4; g++) {
        const int e = g * 256 + tid;
        const int r = e >> 4, dq = (e & 15) * 4;
        float4 v4 = *(const float4*)&Qg[r * DHH + dq];
        Qs[r * 65 + dq + 0] = v4.x;
        Qs[r * 65 + dq + 1] = v4.y;
        Qs[r * 65 + dq + 2] = v4.z;
        Qs[r * 65 + dq + 3] = v4.w;
    }

    float m_prev[4], l_acc[4], acc[4][4];
#pragma unroll
    for (int i = 0; i < 4; i++) {
        m_prev[i] = -INFINITY;
        l_acc[i] = 0.f;
#pragma unroll
        for (int j = 0; j < 4; j++) acc[i][j] = 0.f;
    }

    const int qrow0 = qt * 64 + ty * 4;

    for (int kt = 0; kt <= qt; kt++) {
        __syncthreads();
        const float* Kt = Kg + (size_t)kt * 64 * DHH;
        const float* Vt = Vg + (size_t)kt * 64 * DHH;
#pragma unroll
        for (int g = 0; g < 4; g++) {
            const int e = g * 256 + tid;
            const int r = e >> 4, dq = (e & 15) * 4;
            float4 kv = *(const float4*)&Kt[r * DHH + dq];
            Ks[r * 65 + dq + 0] = kv.x;
            Ks[r * 65 + dq + 1] = kv.y;
            Ks[r * 65 + dq + 2] = kv.z;
            Ks[r * 65 + dq + 3] = kv.w;
            float4 vv = *(const float4*)&Vt[r * DHH + dq];
            Vs[r * 65 + dq + 0] = vv.x;
            Vs[r * 65 + dq + 1] = vv.y;
            Vs[r * 65 + dq + 2] = vv.z;
            Vs[r * 65 + dq + 3] = vv.w;
        }
        __syncthreads();

        float s[4][4];
#pragma unroll
        for (int i = 0; i < 4; i++)
#pragma unroll
            for (int j = 0; j < 4; j++) s[i][j] = 0.f;

#pragma unroll 8
        for (int d = 0; d < 64; d++) {
            float a0 = Qs[(ty * 4 + 0) * 65 + d];
            float a1 = Qs[(ty * 4 + 1) * 65 + d];
            float a2 = Qs[(ty * 4 + 2) * 65 + d];
            float a3 = Qs[(ty * 4 + 3) * 65 + d];
            float b0 = Ks[(tx + 0)  * 65 + d];
            float b1 = Ks[(tx + 16) * 65 + d];
            float b2 = Ks[(tx + 32) * 65 + d];
            float b3 = Ks[(tx + 48) * 65 + d];
            s[0][0] = fmaf(a0, b0, s[0][0]); s[0][1] = fmaf(a0, b1, s[0][1]);
            s[0][2] = fmaf(a0, b2, s[0][2]); s[0][3] = fmaf(a0, b3, s[0][3]);
            s[1][0] = fmaf(a1, b0, s[1][0]); s[1][1] = fmaf(a1, b1, s[1][1]);
            s[1][2] = fmaf(a1, b2, s[1][2]); s[1][3] = fmaf(a1, b3, s[1][3]);
            s[2][0] = fmaf(a2, b0, s[2][0]); s[2][1] = fmaf(a2, b1, s[2][1]);
            s[2][2] = fmaf(a2, b2, s[2][2]); s[2][3] = fmaf(a2, b3, s[2][3]);
            s[3][0] = fmaf(a3, b0, s[3][0]); s[3][1] = fmaf(a3, b1, s[3][1]);
            s[3][2] = fmaf(a3, b2, s[3][2]); s[3][3] = fmaf(a3, b3, s[3][3]);
        }

#pragma unroll
        for (int i = 0; i < 4; i++)
#pragma unroll
            for (int j = 0; j < 4; j++) {
                const int kc = kt * 64 + tx + 16 * j;
                s[i][j] = (kc <= qrow0 + i) ? s[i][j] * 0.125f : -INFINITY;
            }

        float m_new[4], corr[4], p[4][4];
#pragma unroll
        for (int i = 0; i < 4; i++) {
            float tm = fmaxf(fmaxf(s[i][0], s[i][1]), fmaxf(s[i][2], s[i][3]));
#pragma unroll
            for (int off = 8; off > 0; off >>= 1)
                tm = fmaxf(tm, __shfl_xor_sync(0xffffffffu, tm, off, 16));
            m_new[i] = fmaxf(m_prev[i], tm);
            corr[i] = expf(m_prev[i] - m_new[i]);
        }
#pragma unroll
        for (int i = 0; i < 4; i++) {
            float rs = 0.f;
#pragma unroll
            for (int j = 0; j < 4; j++) {
                p[i][j] = expf(s[i][j] - m_new[i]);
                rs += p[i][j];
            }
#pragma unroll
            for (int off = 8; off > 0; off >>= 1)
                rs += __shfl_xor_sync(0xffffffffu, rs, off, 16);
            l_acc[i] = l_acc[i] * corr[i] + rs;
#pragma unroll
            for (int j = 0; j < 4; j++) acc[i][j] *= corr[i];
        }

#pragma unroll
        for (int i = 0; i < 4; i++)
#pragma unroll
            for (int j = 0; j < 4; j++)
                Ps[(ty * 4 + i) * 65 + tx + 16 * j] = p[i][j];
        __syncthreads();

#pragma unroll 8
        for (int k2 = 0; k2 < 64; k2++) {
            float p0 = Ps[(ty * 4 + 0) * 65 + k2];
            float p1 = Ps[(ty * 4 + 1) * 65 + k2];
            float p2 = Ps[(ty * 4 + 2) * 65 + k2];
            float p3 = Ps[(ty * 4 + 3) * 65 + k2];
            float v0 = Vs[k2 * 65 + tx + 0];
            float v1 = Vs[k2 * 65 + tx + 16];
            float v2 = Vs[k2 * 65 + tx + 32];
            float v3 = Vs[k2 * 65 + tx + 48];
            acc[0][0] = fmaf(p0, v0, acc[0][0]); acc[0][1] = fmaf(p0, v1, acc[0][1]);
            acc[0][2] = fmaf(p0, v2, acc[0][2]); acc[0][3] = fmaf(p0, v3, acc[0][3]);
            acc[1][0] = fmaf(p1, v0, acc[1][0]); acc[1][1] = fmaf(p1, v1, acc[1][1]);
            acc[1][2] = fmaf(p1, v2, acc[1][2]); acc[1][3] = fmaf(p1, v3, acc[1][3]);
            acc[2][0] = fmaf(p2, v0, acc[2][0]); acc[2][1] = fmaf(p2, v1, acc[2][1]);
            acc[2][2] = fmaf(p2, v2, acc[2][2]); acc[2][3] = fmaf(p2, v3, acc[2][3]);
            acc[3][0] = fmaf(p3, v0, acc[3][0]); acc[3][1] = fmaf(p3, v1, acc[3][1]);
            acc[3][2] = fmaf(p3, v2, acc[3][2]); acc[3][3] = fmaf(p3, v3, acc[3][3]);
        }
#pragma unroll
        for (int i = 0; i < 4; i++) m_prev[i] = m_new[i];
    }

    float* Yg = g_y + ((size_t)bh * TT + qt * 64) * DHH;
#pragma unroll
    for (int i = 0; i < 4; i++) {
        const float inv_l = 1.f / l_acc[i];
#pragma unroll
        for (int j = 0; j < 4; j++)
            Yg[(ty * 4 + i) * DHH + tx + 16 * j] = acc[i][j] * inv_l;
    }
}

// ---------------------------------------------------------------------------
extern "C" void kernel_launch(void* const* d_in, const int* in_sizes, int n_in,
                              void* d_out, int out_size)
{
    (void)in_sizes; (void)n_in; (void)out_size;
    const float* x     = (const float*)d_in[0];
    const float* W_qkv = (const float*)d_in[2];
    const float* b_qkv = (const float*)d_in[3];
    const float* W_out = (const float*)d_in[4];
    const float* b_out = (const float*)d_in[5];
    float* out = (float*)d_out;

    cudaFuncSetAttribute(attn_kernel,
                         cudaFuncAttributeMaxDynamicSharedMemorySize, SMEM_ATTN);
    cudaFuncSetAttribute(gemm_mma<0>,
                         cudaFuncAttributeMaxDynamicSharedMemorySize, GEMM_SMEM);
    cudaFuncSetAttribute(gemm_mma<1>,
                         cudaFuncAttributeMaxDynamicSharedMemorySize, GEMM_SMEM);

    float* wtq = nullptr; cudaGetSymbolAddress((void**)&wtq, g_wtq);
    float* wto = nullptr; cudaGetSymbolAddress((void**)&wto, g_wto);

    // 0) transpose weights to K-major [n][k]
    transpose_kernel<<<dim3(3072 / 32, 1024 / 32), dim3(32, 8)>>>(W_qkv, wtq, 3072);
    transpose_kernel<<<dim3(1024 / 32, 1024 / 32), dim3(32, 8)>>>(W_out, wto, 1024);

    // 1) QKV projection (mma.sync tf32) + scatter to [B,H,T,DH]
    gemm_mma<0><<<dim3(3072 / 128, M_TOT / 128), 256, GEMM_SMEM>>>(x, wtq, b_qkv, nullptr);

    // 2) RoPE in place
    rope_kernel<<<(BB * HH * TT * 32) / 256, 256>>>();

    // 3) causal flash attention (fp32)
    attn_kernel<<<dim3(TT / 64, BB * HH), 256, SMEM_ATTN>>>();

    // 4) output projection (mma.sync tf32)
    gemm_mma<1><<<dim3(DIMM / 128, M_TOT / 128), 256, GEMM_SMEM>>>(nullptr, wto, b_out, out);
}

// round 4
// speedup vs baseline: 2.7018x; 1.9157x over previous
#include <cuda_runtime.h>
#include <math.h>
#include <stdint.h>

#define BB 2
#define TT 2048
#define DIMM 1024
#define HH 16
#define DHH 64
#define M_TOT (BB*TT)        /* 4096 */

// Scratch (static device globals; allocation is forbidden)
__device__ float g_q[(size_t)BB*HH*TT*DHH];
__device__ float g_k[(size_t)BB*HH*TT*DHH];
__device__ float g_v[(size_t)BB*HH*TT*DHH];
__device__ float g_y[(size_t)BB*HH*TT*DHH];
__device__ float g_wtq[(size_t)3072*1024];   // W_qkv^T  [n][k]
__device__ float g_wto[(size_t)1024*1024];   // W_out^T  [n][k]
__device__ float g_rc[TT*32];                // rope cos table
__device__ float g_rs[TT*32];                // rope sin table

// ---------------------------------------------------------------------------
// Helpers: legacy mma.sync tf32 path (tcgen05 needs sm_103a feature target
// which this harness does not emit).
// ---------------------------------------------------------------------------
__device__ __forceinline__ uint32_t smem_u32(const void* p) {
    uint32_t a;
    asm("{ .reg .u64 t; cvta.to.shared.u64 t, %1; cvt.u32.u64 %0, t; }"
        : "=r"(a) : "l"(p));
    return a;
}
__device__ __forceinline__ uint32_t cvt_tf32(float f) {
    uint32_t u;
    asm("cvt.rna.tf32.f32 %0, %1;" : "=r"(u) : "f"(f));
    return u;
}
#define CP16(sa, gp) \
    asm volatile("cp.async.cg.shared.global [%0], [%1], 16;" :: "r"(sa), "l"(gp))
#define CP_COMMIT() asm volatile("cp.async.commit_group;" ::: "memory")
#define CP_WAIT1()  asm volatile("cp.async.wait_group 1;" ::: "memory")
#define CP_WAIT0()  asm volatile("cp.async.wait_group 0;" ::: "memory")

__device__ __forceinline__ void mma_tf32(float* c, const uint32_t* a,
                                         const uint32_t* b) {
    asm volatile(
        "mma.sync.aligned.m16n8k8.row.col.f32.tf32.tf32.f32 "
        "{%0,%1,%2,%3}, {%4,%5,%6,%7}, {%8,%9}, {%0,%1,%2,%3};"
        : "+f"(c[0]), "+f"(c[1]), "+f"(c[2]), "+f"(c[3])
        : "r"(a[0]), "r"(a[1]), "r"(a[2]), "r"(a[3]), "r"(b[0]), "r"(b[1]));
}

// ---------------------------------------------------------------------------
// Weight transpose: src [1024][C] -> dst [C][1024]  (K-major for mma frags)
// ---------------------------------------------------------------------------
__global__ void transpose_kernel(const float* __restrict__ src,
                                 float* __restrict__ dst, int C)
{
    __shared__ float t[32][33];
    const int c0 = blockIdx.x * 32, r0 = blockIdx.y * 32;
    for (int i = threadIdx.y; i < 32; i += 8)
        t[i][threadIdx.x] = src[(size_t)(r0 + i) * C + c0 + threadIdx.x];
    __syncthreads();
    for (int i = threadIdx.y; i < 32; i += 8)
        dst[(size_t)(c0 + i) * 1024 + r0 + threadIdx.x] = t[threadIdx.x][i];
}

// ---------------------------------------------------------------------------
// mma.sync tf32 GEMM: CTA tile 128x128, BK=32, 8 warps (2x4), warp 64x32.
// (unchanged from passing R3 kernel)
// ---------------------------------------------------------------------------
#define PAD 36
#define ATILE (128 * PAD * 4)
#define STAGE (2 * ATILE)
#define GEMM_SMEM (2 * STAGE)

template <int MODE>
__global__ __launch_bounds__(256) void gemm_mma(
    const float* __restrict__ A, const float* __restrict__ Bt,
    const float* __restrict__ bias, float* __restrict__ out)
{
    extern __shared__ char smem[];
    const uint32_t sb = smem_u32(smem);
    const int tid = threadIdx.x;
    const int wid = tid >> 5;
    const int lane = tid & 31;
    const int gid = lane >> 2;
    const int tg = lane & 3;
    const int mb = (wid >> 2) * 64;
    const int nb = (wid & 3) * 32;
    const int m0 = blockIdx.y * 128;
    const int n0 = blockIdx.x * 128;

    float acc[4][4][4];
#pragma unroll
    for (int mf = 0; mf < 4; mf++)
#pragma unroll
        for (int nf = 0; nf < 4; nf++)
#pragma unroll
            for (int i = 0; i < 4; i++) acc[mf][nf][i] = 0.f;

    auto issue_tile = [&](int c) {
        const int p = c & 1;
        const int k0 = c * 32;
        const uint32_t aBase = sb + p * STAGE;
        const uint32_t bBase = aBase + ATILE;
#pragma unroll
        for (int i = 0; i < 4; i++) {
            const int e = tid + 256 * i;
            const int rr = e >> 3, q = e & 7;
            const float* gp;
            if (MODE == 0) {
                gp = &A[(size_t)(m0 + rr) * 1024 + k0 + q * 4];
            } else {
                const int m = m0 + rr, b = m >> 11, t = m & (TT - 1);
                const int kk = k0 + q * 4, h = kk >> 6, d = kk & 63;
                gp = &g_y[(((size_t)b * HH + h) * TT + t) * DHH + d];
            }
            CP16(aBase + (uint32_t)(rr * PAD + q * 4) * 4, gp);
        }
#pragma unroll
        for (int i = 0; i < 4; i++) {
            const int e = tid + 256 * i;
            const int rr = e >> 3, q = e & 7;
            const float* gp = &Bt[(size_t)(n0 + rr) * 1024 + k0 + q * 4];
            CP16(bBase + (uint32_t)(rr * PAD + q * 4) * 4, gp);
        }
        CP_COMMIT();
    };

    issue_tile(0);
    for (int c = 0; c < 32; c++) {
        if (c + 1 < 32) { issue_tile(c + 1); CP_WAIT1(); }
        else            { CP_WAIT0(); }
        __syncthreads();

        const int p = c & 1;
        const float* As = (const float*)(smem + p * STAGE);
        const float* Bs = (const float*)(smem + p * STAGE + ATILE);
#pragma unroll
        for (int ks = 0; ks < 4; ks++) {
            const int kk = ks * 8;
            uint32_t af[4][4], bf[4][2];
#pragma unroll
            for (int mf = 0; mf < 4; mf++) {
                const float* ap = As + (mb + mf * 16 + gid) * PAD + kk + tg;
                af[mf][0] = cvt_tf32(ap[0]);
                af[mf][1] = cvt_tf32(ap[8 * PAD]);
                af[mf][2] = cvt_tf32(ap[4]);
                af[mf][3] = cvt_tf32(ap[8 * PAD + 4]);
            }
#pragma unroll
            for (int nf = 0; nf < 4; nf++) {
                const float* bp = Bs + (nb + nf * 8 + gid) * PAD + kk + tg;
                bf[nf][0] = cvt_tf32(bp[0]);
                bf[nf][1] = cvt_tf32(bp[4]);
            }
#pragma unroll
            for (int mf = 0; mf < 4; mf++)
#pragma unroll
                for (int nf = 0; nf < 4; nf++)
                    mma_tf32(acc[mf][nf], af[mf], bf[nf]);
        }
        __syncthreads();
    }

#pragma unroll
    for (int mf = 0; mf < 4; mf++) {
        const int r0 = m0 + mb + mf * 16 + gid;
#pragma unroll
        for (int nf = 0; nf < 4; nf++) {
            const int n = n0 + nb + nf * 8 + tg * 2;
            const float bx = bias[n], by = bias[n + 1];
            float2 v0 = make_float2(acc[mf][nf][0] + bx, acc[mf][nf][1] + by);
            float2 v1 = make_float2(acc[mf][nf][2] + bx, acc[mf][nf][3] + by);
            if (MODE == 0) {
                const int which = n >> 10;
                const int rr = n & 1023;
                const int h = rr >> 6, d = rr & 63;
                float* dst = (which == 0) ? g_q : (which == 1) ? g_k : g_v;
                {
                    const int b = r0 >> 11, t = r0 & (TT - 1);
                    *(float2*)&dst[(((size_t)b * HH + h) * TT + t) * DHH + d] = v0;
                }
                {
                    const int m1 = r0 + 8;
                    const int b = m1 >> 11, t = m1 & (TT - 1);
                    *(float2*)&dst[(((size_t)b * HH + h) * TT + t) * DHH + d] = v1;
                }
            } else {
                *(float2*)&out[(size_t)r0 * DIMM + n] = v0;
                *(float2*)&out[(size_t)(r0 + 8) * DIMM + n] = v1;
            }
        }
    }
}

// ---------------------------------------------------------------------------
// RoPE: build cos/sin table once (fp64, 65536 threads), then cheap apply.
// ---------------------------------------------------------------------------
__global__ void build_rope()
{
    const int idx = blockIdx.x * blockDim.x + threadIdx.x;   // 65536
    const int d = idx & 31, t = idx >> 5;
    const float invf = (float)exp(-(double)d * (log(10000.0) / 32.0));
    const float ang = (float)t * invf;
    double sd, cd;
    sincos((double)ang, &sd, &cd);
    g_rc[t * 32 + d] = (float)cd;
    g_rs[t * 32 + d] = (float)sd;
}

__global__ void rope_apply()
{
    const int idx = blockIdx.x * blockDim.x + threadIdx.x;   // 2^21
    const int d  = idx & 31;
    const int t  = (idx >> 5) & (TT - 1);
    const int bh = idx >> 16;
    const float cf = g_rc[t * 32 + d];
    const float sf = g_rs[t * 32 + d];

    const size_t base = ((size_t)bh * TT + t) * DHH;
    const float qa = g_q[base + d], qb = g_q[base + 32 + d];
    g_q[base + d]      = qa * cf - qb * sf;
    g_q[base + 32 + d] = qa * sf + qb * cf;
    const float ka = g_k[base + d], kb = g_k[base + 32 + d];
    g_k[base + d]      = ka * cf - kb * sf;
    g_k[base + 32 + d] = ka * sf + kb * cf;
}

// ---------------------------------------------------------------------------
// Flash attention on mma.sync tf32.
// CTA: 128 Q rows x (b,h). 8 warps, each owns 16 Q rows. K-tiles of 64.
// Q split hi/lo tf32 for S=QK^T (kills Q truncation error); PV single tf32.
// SMEM: Qs[128][68], Ks[64][68], Vt[64][68] (V^T), Ps[128][68].
// ---------------------------------------------------------------------------
#define APAD 68
#define ATTN_SMEM ((128*APAD + 64*APAD + 64*APAD + 128*APAD) * 4)

__global__ __launch_bounds__(256, 2) void attn_mma()
{
    extern __shared__ float sm[];
    float* Qs = sm;                       // [128][APAD]
    float* Ks = Qs + 128 * APAD;          // [64][APAD]
    float* Vt = Ks + 64 * APAD;           // [64][APAD]  (V^T: [d][kc])
    float* Ps = Vt + 64 * APAD;           // [128][APAD]

    const int qt = blockIdx.x;            // 0..15 (128-row q tiles)
    const int bh = blockIdx.y;            // 0..31
    const int tid = threadIdx.x;
    const int wid = tid >> 5;
    const int lane = tid & 31;
    const int gid = lane >> 2;            // 0..7
    const int tg = lane & 3;              // 0..3
    const int q0 = qt * 128;
    const int wrow = wid * 16;            // warp's first local q row

    const float* Qg = g_q + ((size_t)bh * TT + q0) * DHH;
    const float* Kg = g_k + (size_t)bh * TT * DHH;
    const float* Vg = g_v + (size_t)bh * TT * DHH;

    // Load Q tile (x 1/8 softmax scale folded in)
#pragma unroll
    for (int i = 0; i < 8; i++) {
        const int e = tid + 256 * i;
        const int r = e >> 4, c = (e & 15) * 4;
        float4 v = *(const float4*)&Qg[r * DHH + c];
        Qs[r * APAD + c + 0] = v.x * 0.125f;
        Qs[r * APAD + c + 1] = v.y * 0.125f;
        Qs[r * APAD + c + 2] = v.z * 0.125f;
        Qs[r * APAD + c + 3] = v.w * 0.125f;
    }

    float oacc[8][4];
#pragma unroll
    for (int nf = 0; nf < 8; nf++)
#pragma unroll
        for (int i = 0; i < 4; i++) oacc[nf][i] = 0.f;
    float m0v = -INFINITY, m1v = -INFINITY, l0 = 0.f, l1 = 0.f;

    const int r0g = q0 + wrow + gid;
    const int r1g = r0g + 8;
    const int nkt = 2 * qt + 2;

    for (int kt = 0; kt < nkt; kt++) {
        __syncthreads();   // previous tile's readers done
        // Load K tile [kc][d] (coalesced) and V tile transposed -> Vt[d][kc]
#pragma unroll
        for (int i = 0; i < 4; i++) {
            const int e = tid + 256 * i;
            {
                const int r = e >> 4, c = (e & 15) * 4;
                float4 kv = *(const float4*)&Kg[(size_t)(kt * 64 + r) * DHH + c];
                *(float4*)&Ks[r * APAD + c] = kv;
            }
            {
                const int r = e & 63, c = (e >> 6) * 4;   // conflict-free STS
                float4 vv = *(const float4*)&Vg[(size_t)(kt * 64 + r) * DHH + c];
                Vt[(c + 0) * APAD + r] = vv.x;
                Vt[(c + 1) * APAD + r] = vv.y;
                Vt[(c + 2) * APAD + r] = vv.z;
                Vt[(c + 3) * APAD + r] = vv.w;
            }
        }
        __syncthreads();

        if (kt * 64 > q0 + wrow + 15) continue;   // whole warp masked

        // ---- S = Q K^T (Q split hi/lo) ----
        float sacc[8][4];
#pragma unroll
        for (int nf = 0; nf < 8; nf++)
#pragma unroll
            for (int i = 0; i < 4; i++) sacc[nf][i] = 0.f;

#pragma unroll
        for (int ks = 0; ks < 8; ks++) {
            const int kk = ks * 8;
            const float* ap = Qs + (wrow + gid) * APAD + kk + tg;
            const float a0 = ap[0], a1 = ap[8 * APAD];
            const float a2 = ap[4], a3 = ap[8 * APAD + 4];
            uint32_t ah[4] = {cvt_tf32(a0), cvt_tf32(a1), cvt_tf32(a2), cvt_tf32(a3)};
            uint32_t al[4] = {cvt_tf32(a0 - __uint_as_float(ah[0])),
                              cvt_tf32(a1 - __uint_as_float(ah[1])),
                              cvt_tf32(a2 - __uint_as_float(ah[2])),
                              cvt_tf32(a3 - __uint_as_float(ah[3]))};
#pragma unroll
            for (int nf = 0; nf < 8; nf++) {
                const float* bp = Ks + (nf * 8 + gid) * APAD + kk + tg;
                uint32_t bf[2] = {cvt_tf32(bp[0]), cvt_tf32(bp[4])};
                mma_tf32(sacc[nf], ah, bf);
                mma_tf32(sacc[nf], al, bf);
            }
        }

        // ---- causal mask (only last two tiles can cross diagonal) ----
        if (kt >= 2 * qt) {
#pragma unroll
            for (int nf = 0; nf < 8; nf++) {
                const int cb = kt * 64 + nf * 8 + 2 * tg;
                if (cb     > r0g) sacc[nf][0] = -INFINITY;
                if (cb + 1 > r0g) sacc[nf][1] = -INFINITY;
                if (cb     > r1g) sacc[nf][2] = -INFINITY;
                if (cb + 1 > r1g) sacc[nf][3] = -INFINITY;
            }
        }

        // ---- online softmax ----
        float mx0 = -INFINITY, mx1 = -INFINITY;
#pragma unroll
        for (int nf = 0; nf < 8; nf++) {
            mx0 = fmaxf(mx0, fmaxf(sacc[nf][0], sacc[nf][1]));
            mx1 = fmaxf(mx1, fmaxf(sacc[nf][2], sacc[nf][3]));
        }
        mx0 = fmaxf(mx0, __shfl_xor_sync(0xffffffffu, mx0, 1));
        mx0 = fmaxf(mx0, __shfl_xor_sync(0xffffffffu, mx0, 2));
        mx1 = fmaxf(mx1, __shfl_xor_sync(0xffffffffu, mx1, 1));
        mx1 = fmaxf(mx1, __shfl_xor_sync(0xffffffffu, mx1, 2));
        const float mn0 = fmaxf(m0v, mx0), mn1 = fmaxf(m1v, mx1);
        const float c0 = __expf(m0v - mn0), c1 = __expf(m1v - mn1);

        float rs0 = 0.f, rs1 = 0.f;
#pragma unroll
        for (int nf = 0; nf < 8; nf++) {
            sacc[nf][0] = __expf(sacc[nf][0] - mn0);
            sacc[nf][1] = __expf(sacc[nf][1] - mn0);
            sacc[nf][2] = __expf(sacc[nf][2] - mn1);
            sacc[nf][3] = __expf(sacc[nf][3] - mn1);
            rs0 += sacc[nf][0] + sacc[nf][1];
            rs1 += sacc[nf][2] + sacc[nf][3];
        }
        rs0 += __shfl_xor_sync(0xffffffffu, rs0, 1);
        rs0 += __shfl_xor_sync(0xffffffffu, rs0, 2);
        rs1 += __shfl_xor_sync(0xffffffffu, rs1, 1);
        rs1 += __shfl_xor_sync(0xffffffffu, rs1, 2);
        l0 = l0 * c0 + rs0;
        l1 = l1 * c1 + rs1;
        m0v = mn0; m1v = mn1;
#pragma unroll
        for (int nf = 0; nf < 8; nf++) {
            oacc[nf][0] *= c0; oacc[nf][1] *= c0;
            oacc[nf][2] *= c1; oacc[nf][3] *= c1;
        }

        // ---- stage P (warp-private rows; no CTA sync needed) ----
#pragma unroll
        for (int nf = 0; nf < 8; nf++) {
            const int cc = nf * 8 + 2 * tg;
            *(float2*)&Ps[(wrow + gid) * APAD + cc] =
                make_float2(sacc[nf][0], sacc[nf][1]);
            *(float2*)&Ps[(wrow + gid + 8) * APAD + cc] =
                make_float2(sacc[nf][2], sacc[nf][3]);
        }
        __syncwarp();

        // ---- O += P V ----
#pragma unroll
        for (int ks = 0; ks < 8; ks++) {
            const int kk = ks * 8;
            const float* ap = Ps + (wrow + gid) * APAD + kk + tg;
            uint32_t af[4] = {cvt_tf32(ap[0]), cvt_tf32(ap[8 * APAD]),
                              cvt_tf32(ap[4]), cvt_tf32(ap[8 * APAD + 4])};
#pragma unroll
            for (int nf = 0; nf < 8; nf++) {
                const float* bp = Vt + (nf * 8 + gid) * APAD + kk + tg;
                uint32_t bf[2] = {cvt_tf32(bp[0]), cvt_tf32(bp[4])};
                mma_tf32(oacc[nf], af, bf);
            }
        }
        __syncwarp();   // P readers done before next tile overwrites
    }

    // ---- write O / l ----
    const float i0 = 1.f / l0, i1 = 1.f / l1;
    float* Yg = g_y + ((size_t)bh * TT + q0) * DHH;
#pragma unroll
    for (int nf = 0; nf < 8; nf++) {
        const int cc = nf * 8 + 2 * tg;
        *(float2*)&Yg[(wrow + gid) * DHH + cc] =
            make_float2(oacc[nf][0] * i0, oacc[nf][1] * i0);
        *(float2*)&Yg[(wrow + gid + 8) * DHH + cc] =
            make_float2(oacc[nf][2] * i1, oacc[nf][3] * i1);
    }
}

// ---------------------------------------------------------------------------
extern "C" void kernel_launch(void* const* d_in, const int* in_sizes, int n_in,
                              void* d_out, int out_size)
{
    (void)in_sizes; (void)n_in; (void)out_size;
    const float* x     = (const float*)d_in[0];
    const float* W_qkv = (const float*)d_in[2];
    const float* b_qkv = (const float*)d_in[3];
    const float* W_out = (const float*)d_in[4];
    const float* b_out = (const float*)d_in[5];
    float* out = (float*)d_out;

    cudaFuncSetAttribute(attn_mma,
                         cudaFuncAttributeMaxDynamicSharedMemorySize, ATTN_SMEM);
    cudaFuncSetAttribute(gemm_mma<0>,
                         cudaFuncAttributeMaxDynamicSharedMemorySize, GEMM_SMEM);
    cudaFuncSetAttribute(gemm_mma<1>,
                         cudaFuncAttributeMaxDynamicSharedMemorySize, GEMM_SMEM);

    float* wtq = nullptr; cudaGetSymbolAddress((void**)&wtq, g_wtq);
    float* wto = nullptr; cudaGetSymbolAddress((void**)&wto, g_wto);

    // 0) rope table + weight transposes
    build_rope<<<256, 256>>>();
    transpose_kernel<<<dim3(3072 / 32, 1024 / 32), dim3(32, 8)>>>(W_qkv, wtq, 3072);
    transpose_kernel<<<dim3(1024 / 32, 1024 / 32), dim3(32, 8)>>>(W_out, wto, 1024);

    // 1) QKV projection (mma.sync tf32) + scatter to [B,H,T,DH]
    gemm_mma<0><<<dim3(3072 / 128, M_TOT / 128), 256, GEMM_SMEM>>>(x, wtq, b_qkv, nullptr);

    // 2) RoPE in place (table lookup)
    rope_apply<<<(BB * HH * TT * 32) / 256, 256>>>();

    // 3) causal flash attention (mma.sync tf32, split-Q)
    attn_mma<<<dim3(TT / 128, BB * HH), 256, ATTN_SMEM>>>();

    // 4) output projection (mma.sync tf32)
    gemm_mma<1><<<dim3(DIMM / 128, M_TOT / 128), 256, GEMM_SMEM>>>(nullptr, wto, b_out, out);
}

// round 5
// speedup vs baseline: 3.3112x; 1.2256x over previous
#include <cuda_runtime.h>
#include <math.h>
#include <stdint.h>

#define BB 2
#define TT 2048
#define DIMM 1024
#define HH 16
#define DHH 64
#define M_TOT (BB*TT)        /* 4096 */

// Scratch (static device globals; allocation is forbidden)
__device__ float g_q[(size_t)BB*HH*TT*DHH];
__device__ float g_k[(size_t)BB*HH*TT*DHH];
__device__ float g_v[(size_t)BB*HH*TT*DHH];
__device__ float g_y[(size_t)BB*HH*TT*DHH];
__device__ float g_xr[(size_t)M_TOT*DIMM];   // x rounded to tf32
__device__ float g_wtq[(size_t)3072*1024];   // W_qkv^T  [n][k], tf32-rounded
__device__ float g_wto[(size_t)1024*1024];   // W_out^T  [n][k], tf32-rounded
__device__ float g_rc[TT*32];                // rope cos table
__device__ float g_rs[TT*32];                // rope sin table

// ---------------------------------------------------------------------------
// Helpers (legacy mma.sync tf32 path; tcgen05 needs the sm_103a feature
// target which this harness does not emit).
// ---------------------------------------------------------------------------
__device__ __forceinline__ uint32_t smem_u32(const void* p) {
    uint32_t a;
    asm("{ .reg .u64 t; cvta.to.shared.u64 t, %1; cvt.u32.u64 %0, t; }"
        : "=r"(a) : "l"(p));
    return a;
}
__device__ __forceinline__ uint32_t cvt_tf32(float f) {
    uint32_t u;
    asm("cvt.rna.tf32.f32 %0, %1;" : "=r"(u) : "f"(f));
    return u;
}
__device__ __forceinline__ float rnd_tf32(float f) {
    return __uint_as_float(cvt_tf32(f));
}
#define CP16(sa, gp) \
    asm volatile("cp.async.cg.shared.global [%0], [%1], 16;" :: "r"(sa), "l"(gp))
#define CP_COMMIT() asm volatile("cp.async.commit_group;" ::: "memory")
#define CP_WAIT1()  asm volatile("cp.async.wait_group 1;" ::: "memory")
#define CP_WAIT0()  asm volatile("cp.async.wait_group 0;" ::: "memory")

__device__ __forceinline__ void mma_tf32(float* c, const uint32_t* a,
                                         const uint32_t* b) {
    asm volatile(
        "mma.sync.aligned.m16n8k8.row.col.f32.tf32.tf32.f32 "
        "{%0,%1,%2,%3}, {%4,%5,%6,%7}, {%8,%9}, {%0,%1,%2,%3};"
        : "+f"(c[0]), "+f"(c[1]), "+f"(c[2]), "+f"(c[3])
        : "r"(a[0]), "r"(a[1]), "r"(a[2]), "r"(a[3]), "r"(b[0]), "r"(b[1]));
}

// ---------------------------------------------------------------------------
// Round x to tf32 (value-identical to cvt at fragment load)
// ---------------------------------------------------------------------------
__global__ void round_x(const float* __restrict__ x)
{
    const int i = blockIdx.x * blockDim.x + threadIdx.x;   // 1M float4
    float4 v = ((const float4*)x)[i];
    v.x = rnd_tf32(v.x); v.y = rnd_tf32(v.y);
    v.z = rnd_tf32(v.z); v.w = rnd_tf32(v.w);
    ((float4*)g_xr)[i] = v;
}

// ---------------------------------------------------------------------------
// Weight transpose + tf32 rounding: src [1024][C] -> dst [C][1024]
// ---------------------------------------------------------------------------
__global__ void transpose_kernel(const float* __restrict__ src,
                                 float* __restrict__ dst, int C)
{
    __shared__ float t[32][33];
    const int c0 = blockIdx.x * 32, r0 = blockIdx.y * 32;
    for (int i = threadIdx.y; i < 32; i += 8)
        t[i][threadIdx.x] = src[(size_t)(r0 + i) * C + c0 + threadIdx.x];
    __syncthreads();
    for (int i = threadIdx.y; i < 32; i += 8)
        dst[(size_t)(c0 + i) * 1024 + r0 + threadIdx.x] = rnd_tf32(t[threadIdx.x][i]);
}

// ---------------------------------------------------------------------------
// mma.sync tf32 GEMM, CTA 128x128, BK=32, 8 warps, warp 64x32.
// All operands pre-rounded in gmem -> no cvt in the hot loop.
// ---------------------------------------------------------------------------
#define PAD 36
#define ATILE (128 * PAD * 4)
#define STAGE (2 * ATILE)
#define GEMM_SMEM (2 * STAGE)

template <int MODE>
__global__ __launch_bounds__(256) void gemm_mma(
    const float* __restrict__ A, const float* __restrict__ Bt,
    const float* __restrict__ bias, float* __restrict__ out)
{
    extern __shared__ char smem[];
    const uint32_t sb = smem_u32(smem);
    const int tid = threadIdx.x;
    const int wid = tid >> 5;
    const int lane = tid & 31;
    const int gid = lane >> 2;
    const int tg = lane & 3;
    const int mb = (wid >> 2) * 64;
    const int nb = (wid & 3) * 32;
    const int m0 = blockIdx.y * 128;
    const int n0 = blockIdx.x * 128;

    float acc[4][4][4];
#pragma unroll
    for (int mf = 0; mf < 4; mf++)
#pragma unroll
        for (int nf = 0; nf < 4; nf++)
#pragma unroll
            for (int i = 0; i < 4; i++) acc[mf][nf][i] = 0.f;

    auto issue_tile = [&](int c) {
        const int p = c & 1;
        const int k0 = c * 32;
        const uint32_t aBase = sb + p * STAGE;
        const uint32_t bBase = aBase + ATILE;
#pragma unroll
        for (int i = 0; i < 4; i++) {
            const int e = tid + 256 * i;
            const int rr = e >> 3, q = e & 7;
            const float* gp;
            if (MODE == 0) {
                gp = &A[(size_t)(m0 + rr) * 1024 + k0 + q * 4];
            } else {
                const int m = m0 + rr, b = m >> 11, t = m & (TT - 1);
                const int kk = k0 + q * 4, h = kk >> 6, d = kk & 63;
                gp = &g_y[(((size_t)b * HH + h) * TT + t) * DHH + d];
            }
            CP16(aBase + (uint32_t)(rr * PAD + q * 4) * 4, gp);
        }
#pragma unroll
        for (int i = 0; i < 4; i++) {
            const int e = tid + 256 * i;
            const int rr = e >> 3, q = e & 7;
            const float* gp = &Bt[(size_t)(n0 + rr) * 1024 + k0 + q * 4];
            CP16(bBase + (uint32_t)(rr * PAD + q * 4) * 4, gp);
        }
        CP_COMMIT();
    };

    issue_tile(0);
    for (int c = 0; c < 32; c++) {
        if (c + 1 < 32) { issue_tile(c + 1); CP_WAIT1(); }
        else            { CP_WAIT0(); }
        __syncthreads();

        const int p = c & 1;
        const uint32_t* As = (const uint32_t*)(smem + p * STAGE);
        const uint32_t* Bs = (const uint32_t*)(smem + p * STAGE + ATILE);
#pragma unroll
        for (int ks = 0; ks < 4; ks++) {
            const int kk = ks * 8;
            uint32_t af[4][4], bf[4][2];
#pragma unroll
            for (int mf = 0; mf < 4; mf++) {
                const uint32_t* ap = As + (mb + mf * 16 + gid) * PAD + kk + tg;
                af[mf][0] = ap[0];
                af[mf][1] = ap[8 * PAD];
                af[mf][2] = ap[4];
                af[mf][3] = ap[8 * PAD + 4];
            }
#pragma unroll
            for (int nf = 0; nf < 4; nf++) {
                const uint32_t* bp = Bs + (nb + nf * 8 + gid) * PAD + kk + tg;
                bf[nf][0] = bp[0];
                bf[nf][1] = bp[4];
            }
#pragma unroll
            for (int mf = 0; mf < 4; mf++)
#pragma unroll
                for (int nf = 0; nf < 4; nf++)
                    mma_tf32(acc[mf][nf], af[mf], bf[nf]);
        }
        __syncthreads();
    }

#pragma unroll
    for (int mf = 0; mf < 4; mf++) {
        const int r0 = m0 + mb + mf * 16 + gid;
#pragma unroll
        for (int nf = 0; nf < 4; nf++) {
            const int n = n0 + nb + nf * 8 + tg * 2;
            const float bx = bias[n], by = bias[n + 1];
            float2 v0 = make_float2(acc[mf][nf][0] + bx, acc[mf][nf][1] + by);
            float2 v1 = make_float2(acc[mf][nf][2] + bx, acc[mf][nf][3] + by);
            if (MODE == 0) {
                const int which = n >> 10;
                const int rr = n & 1023;
                const int h = rr >> 6, d = rr & 63;
                float* dst = (which == 0) ? g_q : (which == 1) ? g_k : g_v;
                if (which == 2) {   // V: pre-round for attention fragments
                    v0.x = rnd_tf32(v0.x); v0.y = rnd_tf32(v0.y);
                    v1.x = rnd_tf32(v1.x); v1.y = rnd_tf32(v1.y);
                }
                {
                    const int b = r0 >> 11, t = r0 & (TT - 1);
                    *(float2*)&dst[(((size_t)b * HH + h) * TT + t) * DHH + d] = v0;
                }
                {
                    const int m1 = r0 + 8;
                    const int b = m1 >> 11, t = m1 & (TT - 1);
                    *(float2*)&dst[(((size_t)b * HH + h) * TT + t) * DHH + d] = v1;
                }
            } else {
                *(float2*)&out[(size_t)r0 * DIMM + n] = v0;
                *(float2*)&out[(size_t)(r0 + 8) * DIMM + n] = v1;
            }
        }
    }
}

// ---------------------------------------------------------------------------
// RoPE: table build (fp64 once) + apply. K output rounded to tf32.
// ---------------------------------------------------------------------------
__global__ void build_rope()
{
    const int idx = blockIdx.x * blockDim.x + threadIdx.x;   // 65536
    const int d = idx & 31, t = idx >> 5;
    const float invf = (float)exp(-(double)d * (log(10000.0) / 32.0));
    const float ang = (float)t * invf;
    double sd, cd;
    sincos((double)ang, &sd, &cd);
    g_rc[t * 32 + d] = (float)cd;
    g_rs[t * 32 + d] = (float)sd;
}

__global__ void rope_apply()
{
    const int idx = blockIdx.x * blockDim.x + threadIdx.x;   // 2^21
    const int d  = idx & 31;
    const int t  = (idx >> 5) & (TT - 1);
    const int bh = idx >> 16;
    const float cf = g_rc[t * 32 + d];
    const float sf = g_rs[t * 32 + d];

    const size_t base = ((size_t)bh * TT + t) * DHH;
    const float qa = g_q[base + d], qb = g_q[base + 32 + d];
    g_q[base + d]      = qa * cf - qb * sf;
    g_q[base + 32 + d] = qa * sf + qb * cf;
    const float ka = g_k[base + d], kb = g_k[base + 32 + d];
    g_k[base + d]      = rnd_tf32(ka * cf - kb * sf);
    g_k[base + 32 + d] = rnd_tf32(ka * sf + kb * cf);
}

// ---------------------------------------------------------------------------
// Flash attention, mma.sync tf32, cp.async double-buffered K/V.
// CTA: 128 Q rows x (b,h), 8 warps x 16 rows, K tiles of 64.
// Qh/Ql pre-split once in SMEM; K (rounded) K-major pad 68; V (rounded)
// row-major pad 72 (conflict-free transposed fragment reads); P rounded
// at write. SMEM 176128 B -> 1 CTA/SM.
// ---------------------------------------------------------------------------
#define KPAD 68
#define VPAD 72
#define OFF_QH 0
#define OFF_QL (128*KPAD)
#define OFF_KS (2*128*KPAD)
#define OFF_VS (OFF_KS + 2*64*KPAD)
#define OFF_PS (OFF_VS + 2*64*VPAD)
#define ATTN_SMEM ((OFF_PS + 128*KPAD) * 4)

__global__ __launch_bounds__(256) void attn_mma()
{
    extern __shared__ float sm[];
    uint32_t* Qh = (uint32_t*)sm + OFF_QH;
    uint32_t* Ql = (uint32_t*)sm + OFF_QL;
    uint32_t* Ps = (uint32_t*)sm + OFF_PS;
    const uint32_t sb = smem_u32(sm);

    const int qt = blockIdx.x;            // 0..15
    const int bh = blockIdx.y;            // 0..31
    const int tid = threadIdx.x;
    const int wid = tid >> 5;
    const int lane = tid & 31;
    const int gid = lane >> 2;
    const int tg = lane & 3;
    const int q0 = qt * 128;
    const int wrow = wid * 16;

    const float* Qg = g_q + ((size_t)bh * TT + q0) * DHH;
    const float* Kg = g_k + (size_t)bh * TT * DHH;
    const float* Vg = g_v + (size_t)bh * TT * DHH;

    // Load Q, fold 1/8 scale, split hi/lo tf32
#pragma unroll
    for (int i = 0; i < 8; i++) {
        const int e = tid + 256 * i;
        const int r = e >> 4, c = (e & 15) * 4;
        float4 v = *(const float4*)&Qg[r * DHH + c];
        float a[4] = {v.x * 0.125f, v.y * 0.125f, v.z * 0.125f, v.w * 0.125f};
#pragma unroll
        for (int j = 0; j < 4; j++) {
            const uint32_t hi = cvt_tf32(a[j]);
            Qh[r * KPAD + c + j] = hi;
            Ql[r * KPAD + c + j] = cvt_tf32(a[j] - __uint_as_float(hi));
        }
    }

    float oacc[8][4];
#pragma unroll
    for (int nf = 0; nf < 8; nf++)
#pragma unroll
        for (int i = 0; i < 4; i++) oacc[nf][i] = 0.f;
    float m0v = -INFINITY, m1v = -INFINITY, l0 = 0.f, l1 = 0.f;

    const int r0g = q0 + wrow + gid;
    const int r1g = r0g + 8;
    const int nkt = 2 * qt + 2;

    auto issue = [&](int kt) {
        const int st = kt & 1;
        const uint32_t kb = sb + (OFF_KS + st * 64 * KPAD) * 4;
        const uint32_t vb = sb + (OFF_VS + st * 64 * VPAD) * 4;
#pragma unroll
        for (int i = 0; i < 4; i++) {
            const int e = tid + 256 * i;
            const int r = e >> 4, c = (e & 15) * 4;
            CP16(kb + (uint32_t)(r * KPAD + c) * 4,
                 &Kg[(size_t)(kt * 64 + r) * DHH + c]);
            CP16(vb + (uint32_t)(r * VPAD + c) * 4,
                 &Vg[(size_t)(kt * 64 + r) * DHH + c]);
        }
        CP_COMMIT();
    };

    issue(0);
    for (int kt = 0; kt < nkt; kt++) {
        if (kt + 1 < nkt) { issue(kt + 1); CP_WAIT1(); }
        else              { CP_WAIT0(); }
        __syncthreads();

        if (kt * 64 <= q0 + wrow + 15) {
            const int st = kt & 1;
            const uint32_t* Ks = (const uint32_t*)sm + OFF_KS + st * 64 * KPAD;
            const uint32_t* Vs = (const uint32_t*)sm + OFF_VS + st * 64 * VPAD;

            // ---- S = Q K^T (hi + lo) ----
            float sacc[8][4];
#pragma unroll
            for (int nf = 0; nf < 8; nf++)
#pragma unroll
                for (int i = 0; i < 4; i++) sacc[nf][i] = 0.f;

#pragma unroll
            for (int ks = 0; ks < 8; ks++) {
                const int kk = ks * 8;
                const uint32_t* aph = Qh + (wrow + gid) * KPAD + kk + tg;
                const uint32_t* apl = Ql + (wrow + gid) * KPAD + kk + tg;
                uint32_t ah[4] = {aph[0], aph[8 * KPAD], aph[4], aph[8 * KPAD + 4]};
                uint32_t al[4] = {apl[0], apl[8 * KPAD], apl[4], apl[8 * KPAD + 4]};
#pragma unroll
                for (int nf = 0; nf < 8; nf++) {
                    const uint32_t* bp = Ks + (nf * 8 + gid) * KPAD + kk + tg;
                    uint32_t bf[2] = {bp[0], bp[4]};
                    mma_tf32(sacc[nf], ah, bf);
                    mma_tf32(sacc[nf], al, bf);
                }
            }

            // ---- causal mask ----
            if (kt >= 2 * qt) {
#pragma unroll
                for (int nf = 0; nf < 8; nf++) {
                    const int cb = kt * 64 + nf * 8 + 2 * tg;
                    if (cb     > r0g) sacc[nf][0] = -INFINITY;
                    if (cb + 1 > r0g) sacc[nf][1] = -INFINITY;
                    if (cb     > r1g) sacc[nf][2] = -INFINITY;
                    if (cb + 1 > r1g) sacc[nf][3] = -INFINITY;
                }
            }

            // ---- online softmax ----
            float mx0 = -INFINITY, mx1 = -INFINITY;
#pragma unroll
            for (int nf = 0; nf < 8; nf++) {
                mx0 = fmaxf(mx0, fmaxf(sacc[nf][0], sacc[nf][1]));
                mx1 = fmaxf(mx1, fmaxf(sacc[nf][2], sacc[nf][3]));
            }
            mx0 = fmaxf(mx0, __shfl_xor_sync(0xffffffffu, mx0, 1));
            mx0 = fmaxf(mx0, __shfl_xor_sync(0xffffffffu, mx0, 2));
            mx1 = fmaxf(mx1, __shfl_xor_sync(0xffffffffu, mx1, 1));
            mx1 = fmaxf(mx1, __shfl_xor_sync(0xffffffffu, mx1, 2));
            const float mn0 = fmaxf(m0v, mx0), mn1 = fmaxf(m1v, mx1);
            const float c0 = __expf(m0v - mn0), c1 = __expf(m1v - mn1);

            float rs0 = 0.f, rs1 = 0.f;
#pragma unroll
            for (int nf = 0; nf < 8; nf++) {
                sacc[nf][0] = __expf(sacc[nf][0] - mn0);
                sacc[nf][1] = __expf(sacc[nf][1] - mn0);
                sacc[nf][2] = __expf(sacc[nf][2] - mn1);
                sacc[nf][3] = __expf(sacc[nf][3] - mn1);
                rs0 += sacc[nf][0] + sacc[nf][1];
                rs1 += sacc[nf][2] + sacc[nf][3];
            }
            rs0 += __shfl_xor_sync(0xffffffffu, rs0, 1);
            rs0 += __shfl_xor_sync(0xffffffffu, rs0, 2);
            rs1 += __shfl_xor_sync(0xffffffffu, rs1, 1);
            rs1 += __shfl_xor_sync(0xffffffffu, rs1, 2);
            l0 = l0 * c0 + rs0;
            l1 = l1 * c1 + rs1;
            m0v = mn0; m1v = mn1;
#pragma unroll
            for (int nf = 0; nf < 8; nf++) {
                oacc[nf][0] *= c0; oacc[nf][1] *= c0;
                oacc[nf][2] *= c1; oacc[nf][3] *= c1;
            }

            // ---- stage P, rounded (warp-private rows) ----
#pragma unroll
            for (int nf = 0; nf < 8; nf++) {
                const int cc = nf * 8 + 2 * tg;
                uint32_t* p0 = &Ps[(wrow + gid) * KPAD + cc];
                uint32_t* p1 = &Ps[(wrow + gid + 8) * KPAD + cc];
                p0[0] = cvt_tf32(sacc[nf][0]); p0[1] = cvt_tf32(sacc[nf][1]);
                p1[0] = cvt_tf32(sacc[nf][2]); p1[1] = cvt_tf32(sacc[nf][3]);
            }
            __syncwarp();

            // ---- O += P V  (V read transposed from row-major, pad 72) ----
#pragma unroll
            for (int ks = 0; ks < 8; ks++) {
                const int kk = ks * 8;
                const uint32_t* ap = Ps + (wrow + gid) * KPAD + kk + tg;
                uint32_t af[4] = {ap[0], ap[8 * KPAD], ap[4], ap[8 * KPAD + 4]};
#pragma unroll
                for (int nf = 0; nf < 8; nf++) {
                    const uint32_t* bp = Vs + (kk + tg) * VPAD + nf * 8 + gid;
                    uint32_t bf[2] = {bp[0], bp[4 * VPAD]};
                    mma_tf32(oacc[nf], af, bf);
                }
            }
            __syncwarp();
        }
        __syncthreads();   // stage consumers done before next cp.async overwrite
    }

    // ---- write O normalized, rounded to tf32 (value-identical to gemm<1>
    //      fragment cvt) ----
    const float i0 = 1.f / l0, i1 = 1.f / l1;
    float* Yg = g_y + ((size_t)bh * TT + q0) * DHH;
#pragma unroll
    for (int nf = 0; nf < 8; nf++) {
        const int cc = nf * 8 + 2 * tg;
        *(float2*)&Yg[(wrow + gid) * DHH + cc] =
            make_float2(rnd_tf32(oacc[nf][0] * i0), rnd_tf32(oacc[nf][1] * i0));
        *(float2*)&Yg[(wrow + gid + 8) * DHH + cc] =
            make_float2(rnd_tf32(oacc[nf][2] * i1), rnd_tf32(oacc[nf][3] * i1));
    }
}

// ---------------------------------------------------------------------------
extern "C" void kernel_launch(void* const* d_in, const int* in_sizes, int n_in,
                              void* d_out, int out_size)
{
    (void)in_sizes; (void)n_in; (void)out_size;
    const float* x     = (const float*)d_in[0];
    const float* W_qkv = (const float*)d_in[2];
    const float* b_qkv = (const float*)d_in[3];
    const float* W_out = (const float*)d_in[4];
    const float* b_out = (const float*)d_in[5];
    float* out = (float*)d_out;

    cudaFuncSetAttribute(attn_mma,
                         cudaFuncAttributeMaxDynamicSharedMemorySize, ATTN_SMEM);
    cudaFuncSetAttribute(gemm_mma<0>,
                         cudaFuncAttributeMaxDynamicSharedMemorySize, GEMM_SMEM);
    cudaFuncSetAttribute(gemm_mma<1>,
                         cudaFuncAttributeMaxDynamicSharedMemorySize, GEMM_SMEM);

    float* wtq = nullptr; cudaGetSymbolAddress((void**)&wtq, g_wtq);
    float* wto = nullptr; cudaGetSymbolAddress((void**)&wto, g_wto);
    float* xr  = nullptr; cudaGetSymbolAddress((void**)&xr, g_xr);

    // 0) prep: rope table, rounded x, rounded transposed weights
    build_rope<<<256, 256>>>();
    round_x<<<(M_TOT * DIMM / 4) / 256, 256>>>(x);
    transpose_kernel<<<dim3(3072 / 32, 1024 / 32), dim3(32, 8)>>>(W_qkv, wtq, 3072);
    transpose_kernel<<<dim3(1024 / 32, 1024 / 32), dim3(32, 8)>>>(W_out, wto, 1024);

    // 1) QKV projection
    gemm_mma<0><<<dim3(3072 / 128, M_TOT / 128), 256, GEMM_SMEM>>>(xr, wtq, b_qkv, nullptr);

    // 2) RoPE (K rounded at write)
    rope_apply<<<(BB * HH * TT * 32) / 256, 256>>>();

    // 3) causal flash attention
    attn_mma<<<dim3(TT / 128, BB * HH), 256, ATTN_SMEM>>>();

    // 4) output projection
    gemm_mma<1><<<dim3(DIMM / 128, M_TOT / 128), 256, GEMM_SMEM>>>(nullptr, wto, b_out, out);
}

// round 6
// speedup vs baseline: 3.3929x; 1.0247x over previous
#include <cuda_runtime.h>
#include <math.h>
#include <stdint.h>

#define BB 2
#define TT 2048
#define DIMM 1024
#define HH 16
#define DHH 64
#define M_TOT (BB*TT)        /* 4096 */

// Scratch (static device globals; allocation is forbidden)
__device__ float g_q[(size_t)BB*HH*TT*DHH];
__device__ float g_k[(size_t)BB*HH*TT*DHH];
__device__ float g_v[(size_t)BB*HH*TT*DHH];
__device__ float g_y[(size_t)BB*HH*TT*DHH];
__device__ float g_xr[(size_t)M_TOT*DIMM];   // x rounded+k-permuted
__device__ float g_wtq[(size_t)3072*1024];   // W_qkv^T [n][k'] rounded+perm
__device__ float g_wto[(size_t)1024*1024];   // W_out^T [n][k'] rounded+perm
__device__ float g_rc[TT*32];                // rope cos table
__device__ float g_rs[TT*32];                // rope sin table

// k-permutation within 8-blocks: thread tg's pair (tg, tg+4) -> (2tg, 2tg+1)
__host__ __device__ __forceinline__ int kperm8(int j) {
    return ((j & 3) << 1) | (j >> 2);
}

// ---------------------------------------------------------------------------
// Helpers (legacy mma.sync tf32; tcgen05 needs the sm_103a feature target
// which this harness does not emit).
// ---------------------------------------------------------------------------
__device__ __forceinline__ uint32_t smem_u32(const void* p) {
    uint32_t a;
    asm("{ .reg .u64 t; cvta.to.shared.u64 t, %1; cvt.u32.u64 %0, t; }"
        : "=r"(a) : "l"(p));
    return a;
}
__device__ __forceinline__ uint32_t cvt_tf32(float f) {
    uint32_t u;
    asm("cvt.rna.tf32.f32 %0, %1;" : "=r"(u) : "f"(f));
    return u;
}
__device__ __forceinline__ float rnd_tf32(float f) {
    return __uint_as_float(cvt_tf32(f));
}
#define CP16(sa, gp) \
    asm volatile("cp.async.cg.shared.global [%0], [%1], 16;" :: "r"(sa), "l"(gp))
#define CP_COMMIT() asm volatile("cp.async.commit_group;" ::: "memory")
#define CP_WAIT1()  asm volatile("cp.async.wait_group 1;" ::: "memory")
#define CP_WAIT0()  asm volatile("cp.async.wait_group 0;" ::: "memory")

__device__ __forceinline__ void mma_tf32(float* c, const uint32_t* a,
                                         const uint32_t* b) {
    asm volatile(
        "mma.sync.aligned.m16n8k8.row.col.f32.tf32.tf32.f32 "
        "{%0,%1,%2,%3}, {%4,%5,%6,%7}, {%8,%9}, {%0,%1,%2,%3};"
        : "+f"(c[0]), "+f"(c[1]), "+f"(c[2]), "+f"(c[3])
        : "r"(a[0]), "r"(a[1]), "r"(a[2]), "r"(a[3]), "r"(b[0]), "r"(b[1]));
}

// ---------------------------------------------------------------------------
// Round x to tf32 + permute k within 8-blocks.
// out[8i + {0..7}] = rnd(in[8i + {0,4,1,5,2,6,3,7}])
// ---------------------------------------------------------------------------
__global__ void round_x(const float* __restrict__ x)
{
    const int i = blockIdx.x * blockDim.x + threadIdx.x;   // 512K 8-blocks
    float4 a = ((const float4*)x)[2 * i];
    float4 b = ((const float4*)x)[2 * i + 1];
    float4 o0 = make_float4(rnd_tf32(a.x), rnd_tf32(b.x), rnd_tf32(a.y), rnd_tf32(b.y));
    float4 o1 = make_float4(rnd_tf32(a.z), rnd_tf32(b.z), rnd_tf32(a.w), rnd_tf32(b.w));
    ((float4*)g_xr)[2 * i] = o0;
    ((float4*)g_xr)[2 * i + 1] = o1;
}

// ---------------------------------------------------------------------------
// Weight transpose + round + k-permute: src [1024][C] -> dst [C][1024']
// ---------------------------------------------------------------------------
__global__ void transpose_kernel(const float* __restrict__ src,
                                 float* __restrict__ dst, int C)
{
    __shared__ float t[32][33];
    const int c0 = blockIdx.x * 32, r0 = blockIdx.y * 32;
    const int tx = threadIdx.x;
    for (int i = threadIdx.y; i < 32; i += 8)
        t[i][tx] = src[(size_t)(r0 + i) * C + c0 + tx];
    __syncthreads();
    const int kp = (tx & 24) | kperm8(tx & 7);
    for (int i = threadIdx.y; i < 32; i += 8)
        dst[(size_t)(c0 + i) * 1024 + r0 + kp] = rnd_tf32(t[tx][i]);
}

// ---------------------------------------------------------------------------
// mma.sync tf32 GEMM, CTA 128x128, BK=32, 8 warps, warp 64x32.
// Operands pre-rounded AND k-permuted in gmem -> paired LDS.64 fragment loads.
// PAD=40: row stride 8 mod 32 -> conflict-free 64-bit LDS.
// ---------------------------------------------------------------------------
#define PAD 40
#define ATILE (128 * PAD * 4)
#define STAGE (2 * ATILE)
#define GEMM_SMEM (2 * STAGE)   /* 163840 */

template <int MODE>
__global__ __launch_bounds__(256) void gemm_mma(
    const float* __restrict__ A, const float* __restrict__ Bt,
    const float* __restrict__ bias, float* __restrict__ out)
{
    extern __shared__ char smem[];
    const uint32_t sb = smem_u32(smem);
    const int tid = threadIdx.x;
    const int wid = tid >> 5;
    const int lane = tid & 31;
    const int gid = lane >> 2;
    const int tg = lane & 3;
    const int mb = (wid >> 2) * 64;
    const int nb = (wid & 3) * 32;
    const int m0 = blockIdx.y * 128;
    const int n0 = blockIdx.x * 128;

    float acc[4][4][4];
#pragma unroll
    for (int mf = 0; mf < 4; mf++)
#pragma unroll
        for (int nf = 0; nf < 4; nf++)
#pragma unroll
            for (int i = 0; i < 4; i++) acc[mf][nf][i] = 0.f;

    auto issue_tile = [&](int c) {
        const int p = c & 1;
        const int k0 = c * 32;
        const uint32_t aBase = sb + p * STAGE;
        const uint32_t bBase = aBase + ATILE;
#pragma unroll
        for (int i = 0; i < 4; i++) {
            const int e = tid + 256 * i;
            const int rr = e >> 3, q = e & 7;
            const float* gp;
            if (MODE == 0) {
                gp = &A[(size_t)(m0 + rr) * 1024 + k0 + q * 4];
            } else {
                const int m = m0 + rr, b = m >> 11, t = m & (TT - 1);
                const int kk = k0 + q * 4, h = kk >> 6, d = kk & 63;
                gp = &g_y[(((size_t)b * HH + h) * TT + t) * DHH + d];
            }
            CP16(aBase + (uint32_t)(rr * PAD + q * 4) * 4, gp);
        }
#pragma unroll
        for (int i = 0; i < 4; i++) {
            const int e = tid + 256 * i;
            const int rr = e >> 3, q = e & 7;
            const float* gp = &Bt[(size_t)(n0 + rr) * 1024 + k0 + q * 4];
            CP16(bBase + (uint32_t)(rr * PAD + q * 4) * 4, gp);
        }
        CP_COMMIT();
    };

    issue_tile(0);
    for (int c = 0; c < 32; c++) {
        if (c + 1 < 32) { issue_tile(c + 1); CP_WAIT1(); }
        else            { CP_WAIT0(); }
        __syncthreads();

        const int p = c & 1;
        const uint32_t* As = (const uint32_t*)(smem + p * STAGE);
        const uint32_t* Bs = (const uint32_t*)(smem + p * STAGE + ATILE);
#pragma unroll
        for (int ks = 0; ks < 4; ks++) {
            const int kk = ks * 8 + 2 * tg;
            uint32_t af[4][4], bf[4][2];
#pragma unroll
            for (int mf = 0; mf < 4; mf++) {
                const uint32_t* ap = As + (mb + mf * 16 + gid) * PAD + kk;
                uint2 lo = *(const uint2*)ap;
                uint2 hi = *(const uint2*)(ap + 8 * PAD);
                af[mf][0] = lo.x; af[mf][2] = lo.y;
                af[mf][1] = hi.x; af[mf][3] = hi.y;
            }
#pragma unroll
            for (int nf = 0; nf < 4; nf++) {
                const uint32_t* bp = Bs + (nb + nf * 8 + gid) * PAD + kk;
                uint2 v = *(const uint2*)bp;
                bf[nf][0] = v.x; bf[nf][1] = v.y;
            }
#pragma unroll
            for (int mf = 0; mf < 4; mf++)
#pragma unroll
                for (int nf = 0; nf < 4; nf++)
                    mma_tf32(acc[mf][nf], af[mf], bf[nf]);
        }
        __syncthreads();
    }

#pragma unroll
    for (int mf = 0; mf < 4; mf++) {
        const int r0 = m0 + mb + mf * 16 + gid;
#pragma unroll
        for (int nf = 0; nf < 4; nf++) {
            const int n = n0 + nb + nf * 8 + tg * 2;
            const float bx = bias[n], by = bias[n + 1];
            float2 v0 = make_float2(acc[mf][nf][0] + bx, acc[mf][nf][1] + by);
            float2 v1 = make_float2(acc[mf][nf][2] + bx, acc[mf][nf][3] + by);
            if (MODE == 0) {
                const int which = n >> 10;
                const int rr = n & 1023;
                const int h = rr >> 6, d = rr & 63;
                float* dst = (which == 0) ? g_q : (which == 1) ? g_k : g_v;
                const int b0i = r0 >> 11, t0i = r0 & (TT - 1);
                const int m1 = r0 + 8;
                const int b1i = m1 >> 11, t1i = m1 & (TT - 1);
                float* d0 = &dst[(((size_t)b0i * HH + h) * TT + t0i) * DHH];
                float* d1 = &dst[(((size_t)b1i * HH + h) * TT + t1i) * DHH];
                if (which == 2) {
                    // V: round + permute d within 8-blocks (scalar stores)
                    const int p0 = (d & 56) | kperm8(d & 7);
                    const int p1 = (d & 56) | kperm8((d + 1) & 7);
                    d0[p0] = rnd_tf32(v0.x); d0[p1] = rnd_tf32(v0.y);
                    d1[p0] = rnd_tf32(v1.x); d1[p1] = rnd_tf32(v1.y);
                } else {
                    *(float2*)&d0[d] = v0;
                    *(float2*)&d1[d] = v1;
                }
            } else {
                *(float2*)&out[(size_t)r0 * DIMM + n] = v0;
                *(float2*)&out[(size_t)(r0 + 8) * DIMM + n] = v1;
            }
        }
    }
}

// ---------------------------------------------------------------------------
// RoPE: table build (fp64 once) + apply. Writes q,k with d permuted within
// 8-blocks (matches attention fragment pairing); k rounded to tf32.
// ---------------------------------------------------------------------------
__global__ void build_rope()
{
    const int idx = blockIdx.x * blockDim.x + threadIdx.x;   // 65536
    const int d = idx & 31, t = idx >> 5;
    const float invf = (float)exp(-(double)d * (log(10000.0) / 32.0));
    const float ang = (float)t * invf;
    double sd, cd;
    sincos((double)ang, &sd, &cd);
    g_rc[t * 32 + d] = (float)cd;
    g_rs[t * 32 + d] = (float)sd;
}

__global__ void rope_apply()
{
    const int idx = blockIdx.x * blockDim.x + threadIdx.x;   // 2^21
    const int d  = idx & 31;
    const int t  = (idx >> 5) & (TT - 1);
    const int bh = idx >> 16;
    const float cf = g_rc[t * 32 + d];
    const float sf = g_rs[t * 32 + d];
    const int dp = (d & 24) | kperm8(d & 7);   // permuted position

    const size_t base = ((size_t)bh * TT + t) * DHH;
    const float qa = g_q[base + d], qb = g_q[base + 32 + d];
    const float ka = g_k[base + d], kb = g_k[base + 32 + d];
    g_q[base + dp]      = qa * cf - qb * sf;
    g_q[base + 32 + dp] = qa * sf + qb * cf;
    g_k[base + dp]      = rnd_tf32(ka * cf - kb * sf);
    g_k[base + 32 + dp] = rnd_tf32(ka * sf + kb * cf);
}

// ---------------------------------------------------------------------------
// Flash attention, mma.sync tf32, cp.async double-buffered K/V.
// q,k permuted in gmem -> paired LDS.64 S-loop fragments (pad 72).
// V d-permuted -> O emerges permuted -> y stored in gemm<1>'s layout.
// ---------------------------------------------------------------------------
#define QPAD 72
#define VPAD 72
#define PPAD 68
#define OFF_QH 0
#define OFF_QL (128*QPAD)
#define OFF_KS (2*128*QPAD)
#define OFF_VS (OFF_KS + 2*64*QPAD)
#define OFF_PS (OFF_VS + 2*64*VPAD)
#define ATTN_SMEM ((OFF_PS + 128*PPAD) * 4)   /* 182272 */

__global__ __launch_bounds__(256) void attn_mma()
{
    extern __shared__ float sm[];
    uint32_t* Qh = (uint32_t*)sm + OFF_QH;
    uint32_t* Ql = (uint32_t*)sm + OFF_QL;
    uint32_t* Ps = (uint32_t*)sm + OFF_PS;
    const uint32_t sb = smem_u32(sm);

    const int qt = gridDim.x - 1 - blockIdx.x;   // heavy tiles first
    const int bh = blockIdx.y;
    const int tid = threadIdx.x;
    const int wid = tid >> 5;
    const int lane = tid & 31;
    const int gid = lane >> 2;
    const int tg = lane & 3;
    const int q0 = qt * 128;
    const int wrow = wid * 16;

    const float* Qg = g_q + ((size_t)bh * TT + q0) * DHH;
    const float* Kg = g_k + (size_t)bh * TT * DHH;
    const float* Vg = g_v + (size_t)bh * TT * DHH;

    // Load Q (already d-permuted in gmem), fold 1/8 scale, split hi/lo
#pragma unroll
    for (int i = 0; i < 8; i++) {
        const int e = tid + 256 * i;
        const int r = e >> 4, c = (e & 15) * 4;
        float4 v = *(const float4*)&Qg[r * DHH + c];
        float a[4] = {v.x * 0.125f, v.y * 0.125f, v.z * 0.125f, v.w * 0.125f};
#pragma unroll
        for (int j = 0; j < 4; j++) {
            const uint32_t hi = cvt_tf32(a[j]);
            Qh[r * QPAD + c + j] = hi;
            Ql[r * QPAD + c + j] = cvt_tf32(a[j] - __uint_as_float(hi));
        }
    }

    float oacc[8][4];
#pragma unroll
    for (int nf = 0; nf < 8; nf++)
#pragma unroll
        for (int i = 0; i < 4; i++) oacc[nf][i] = 0.f;
    float m0v = -INFINITY, m1v = -INFINITY, l0 = 0.f, l1 = 0.f;

    const int r0g = q0 + wrow + gid;
    const int r1g = r0g + 8;
    const int nkt = 2 * qt + 2;

    auto issue = [&](int kt) {
        const int st = kt & 1;
        const uint32_t kb = sb + (OFF_KS + st * 64 * QPAD) * 4;
        const uint32_t vb = sb + (OFF_VS + st * 64 * VPAD) * 4;
#pragma unroll
        for (int i = 0; i < 4; i++) {
            const int e = tid + 256 * i;
            const int r = e >> 4, c = (e & 15) * 4;
            CP16(kb + (uint32_t)(r * QPAD + c) * 4,
                 &Kg[(size_t)(kt * 64 + r) * DHH + c]);
            CP16(vb + (uint32_t)(r * VPAD + c) * 4,
                 &Vg[(size_t)(kt * 64 + r) * DHH + c]);
        }
        CP_COMMIT();
    };

    issue(0);
    for (int kt = 0; kt < nkt; kt++) {
        if (kt + 1 < nkt) { issue(kt + 1); CP_WAIT1(); }
        else              { CP_WAIT0(); }
        __syncthreads();

        if (kt * 64 <= q0 + wrow + 15) {
            const int st = kt & 1;
            const uint32_t* Ks = (const uint32_t*)sm + OFF_KS + st * 64 * QPAD;
            const uint32_t* Vs = (const uint32_t*)sm + OFF_VS + st * 64 * VPAD;

            // ---- S = Q K^T (hi + lo), paired LDS.64 frags ----
            float sacc[8][4];
#pragma unroll
            for (int nf = 0; nf < 8; nf++)
#pragma unroll
                for (int i = 0; i < 4; i++) sacc[nf][i] = 0.f;

#pragma unroll
            for (int ks = 0; ks < 8; ks++) {
                const int kk = ks * 8 + 2 * tg;
                const uint32_t* aph = Qh + (wrow + gid) * QPAD + kk;
                const uint32_t* apl = Ql + (wrow + gid) * QPAD + kk;
                uint2 h0 = *(const uint2*)aph;
                uint2 h1 = *(const uint2*)(aph + 8 * QPAD);
                uint2 l0v = *(const uint2*)apl;
                uint2 l1v = *(const uint2*)(apl + 8 * QPAD);
                uint32_t ah[4] = {h0.x, h1.x, h0.y, h1.y};
                uint32_t al[4] = {l0v.x, l1v.x, l0v.y, l1v.y};
#pragma unroll
                for (int nf = 0; nf < 8; nf++) {
                    uint2 bv = *(const uint2*)(Ks + (nf * 8 + gid) * QPAD + kk);
                    uint32_t bf[2] = {bv.x, bv.y};
                    mma_tf32(sacc[nf], ah, bf);
                    mma_tf32(sacc[nf], al, bf);
                }
            }

            // ---- causal mask ----
            if (kt >= 2 * qt) {
#pragma unroll
                for (int nf = 0; nf < 8; nf++) {
                    const int cb = kt * 64 + nf * 8 + 2 * tg;
                    if (cb     > r0g) sacc[nf][0] = -INFINITY;
                    if (cb + 1 > r0g) sacc[nf][1] = -INFINITY;
                    if (cb     > r1g) sacc[nf][2] = -INFINITY;
                    if (cb + 1 > r1g) sacc[nf][3] = -INFINITY;
                }
            }

            // ---- online softmax ----
            float mx0 = -INFINITY, mx1 = -INFINITY;
#pragma unroll
            for (int nf = 0; nf < 8; nf++) {
                mx0 = fmaxf(mx0, fmaxf(sacc[nf][0], sacc[nf][1]));
                mx1 = fmaxf(mx1, fmaxf(sacc[nf][2], sacc[nf][3]));
            }
            mx0 = fmaxf(mx0, __shfl_xor_sync(0xffffffffu, mx0, 1));
            mx0 = fmaxf(mx0, __shfl_xor_sync(0xffffffffu, mx0, 2));
            mx1 = fmaxf(mx1, __shfl_xor_sync(0xffffffffu, mx1, 1));
            mx1 = fmaxf(mx1, __shfl_xor_sync(0xffffffffu, mx1, 2));
            const float mn0 = fmaxf(m0v, mx0), mn1 = fmaxf(m1v, mx1);
            const float c0 = __expf(m0v - mn0), c1 = __expf(m1v - mn1);

            float rs0 = 0.f, rs1 = 0.f;
#pragma unroll
            for (int nf = 0; nf < 8; nf++) {
                sacc[nf][0] = __expf(sacc[nf][0] - mn0);
                sacc[nf][1] = __expf(sacc[nf][1] - mn0);
                sacc[nf][2] = __expf(sacc[nf][2] - mn1);
                sacc[nf][3] = __expf(sacc[nf][3] - mn1);
                rs0 += sacc[nf][0] + sacc[nf][1];
                rs1 += sacc[nf][2] + sacc[nf][3];
            }
            rs0 += __shfl_xor_sync(0xffffffffu, rs0, 1);
            rs0 += __shfl_xor_sync(0xffffffffu, rs0, 2);
            rs1 += __shfl_xor_sync(0xffffffffu, rs1, 1);
            rs1 += __shfl_xor_sync(0xffffffffu, rs1, 2);
            l0 = l0 * c0 + rs0;
            l1 = l1 * c1 + rs1;
            m0v = mn0; m1v = mn1;
#pragma unroll
            for (int nf = 0; nf < 8; nf++) {
                oacc[nf][0] *= c0; oacc[nf][1] *= c0;
                oacc[nf][2] *= c1; oacc[nf][3] *= c1;
            }

            // ---- stage P, rounded (warp-private rows, key-dim unpermuted) ----
#pragma unroll
            for (int nf = 0; nf < 8; nf++) {
                const int cc = nf * 8 + 2 * tg;
                uint32_t* p0 = &Ps[(wrow + gid) * PPAD + cc];
                uint32_t* p1 = &Ps[(wrow + gid + 8) * PPAD + cc];
                p0[0] = cvt_tf32(sacc[nf][0]); p0[1] = cvt_tf32(sacc[nf][1]);
                p1[0] = cvt_tf32(sacc[nf][2]); p1[1] = cvt_tf32(sacc[nf][3]);
            }
            __syncwarp();

            // ---- O += P V ----
#pragma unroll
            for (int ks = 0; ks < 8; ks++) {
                const int kk = ks * 8;
                const uint32_t* ap = Ps + (wrow + gid) * PPAD + kk + tg;
                uint32_t af[4] = {ap[0], ap[8 * PPAD], ap[4], ap[8 * PPAD + 4]};
#pragma unroll
                for (int nf = 0; nf < 8; nf++) {
                    const uint32_t* bp = Vs + (kk + tg) * VPAD + nf * 8 + gid;
                    uint32_t bf[2] = {bp[0], bp[4 * VPAD]};
                    mma_tf32(oacc[nf], af, bf);
                }
            }
            __syncwarp();
        }
        __syncthreads();
    }

    // ---- write O (columns are permuted-d = gemm<1>'s expected layout) ----
    const float i0 = 1.f / l0, i1 = 1.f / l1;
    float* Yg = g_y + ((size_t)bh * TT + q0) * DHH;
#pragma unroll
    for (int nf = 0; nf < 8; nf++) {
        const int cc = nf * 8 + 2 * tg;
        *(float2*)&Yg[(wrow + gid) * DHH + cc] =
            make_float2(rnd_tf32(oacc[nf][0] * i0), rnd_tf32(oacc[nf][1] * i0));
        *(float2*)&Yg[(wrow + gid + 8) * DHH + cc] =
            make_float2(rnd_tf32(oacc[nf][2] * i1), rnd_tf32(oacc[nf][3] * i1));
    }
}

// ---------------------------------------------------------------------------
extern "C" void kernel_launch(void* const* d_in, const int* in_sizes, int n_in,
                              void* d_out, int out_size)
{
    (void)in_sizes; (void)n_in; (void)out_size;
    const float* x     = (const float*)d_in[0];
    const float* W_qkv = (const float*)d_in[2];
    const float* b_qkv = (const float*)d_in[3];
    const float* W_out = (const float*)d_in[4];
    const float* b_out = (const float*)d_in[5];
    float* out = (float*)d_out;

    cudaFuncSetAttribute(attn_mma,
                         cudaFuncAttributeMaxDynamicSharedMemorySize, ATTN_SMEM);
    cudaFuncSetAttribute(gemm_mma<0>,
                         cudaFuncAttributeMaxDynamicSharedMemorySize, GEMM_SMEM);
    cudaFuncSetAttribute(gemm_mma<1>,
                         cudaFuncAttributeMaxDynamicSharedMemorySize, GEMM_SMEM);

    float* wtq = nullptr; cudaGetSymbolAddress((void**)&wtq, g_wtq);
    float* wto = nullptr; cudaGetSymbolAddress((void**)&wto, g_wto);
    float* xr  = nullptr; cudaGetSymbolAddress((void**)&xr, g_xr);

    // 0) prep: rope table, rounded+permuted x, rounded+permuted weights^T
    build_rope<<<256, 256>>>();
    round_x<<<(M_TOT * DIMM / 8) / 256, 256>>>(x);
    transpose_kernel<<<dim3(3072 / 32, 1024 / 32), dim3(32, 8)>>>(W_qkv, wtq, 3072);
    transpose_kernel<<<dim3(1024 / 32, 1024 / 32), dim3(32, 8)>>>(W_out, wto, 1024);

    // 1) QKV projection
    gemm_mma<0><<<dim3(3072 / 128, M_TOT / 128), 256, GEMM_SMEM>>>(xr, wtq, b_qkv, nullptr);

    // 2) RoPE (q,k written d-permuted; k rounded)
    rope_apply<<<(BB * HH * TT * 32) / 256, 256>>>();

    // 3) causal flash attention
    attn_mma<<<dim3(TT / 128, BB * HH), 256, ATTN_SMEM>>>();

    // 4) output projection
    gemm_mma<1><<<dim3(DIMM / 128, M_TOT / 128), 256, GEMM_SMEM>>>(nullptr, wto, b_out, out);
}

// round 7
// speedup vs baseline: 3.6910x; 1.0878x over previous
#include <cuda_runtime.h>
#include <math.h>
#include <stdint.h>

#define BB 2
#define TT 2048
#define DIMM 1024
#define HH 16
#define DHH 64
#define M_TOT (BB*TT)        /* 4096 */

// Scratch (static device globals; allocation is forbidden)
__device__ float g_q[(size_t)BB*HH*TT*DHH];   // [b,h,t,d']  (d k-permuted)
__device__ float g_k[(size_t)BB*HH*TT*DHH];   // [b,h,t,d']  (d k-permuted)
__device__ float g_v[(size_t)BB*HH*TT*DHH];   // [b,h,d,t]   TRANSPOSED, natural d
__device__ float g_y[(size_t)BB*HH*TT*DHH];   // [b,h,t,d']  (d k-permuted)
__device__ float g_xr[(size_t)M_TOT*DIMM];    // x rounded+k-permuted
__device__ float g_wtq[(size_t)3072*1024];    // W_qkv^T [n][k'] rounded+perm
__device__ float g_wto[(size_t)1024*1024];    // W_out^T [n][k'] rounded+perm
__device__ float g_rc[TT*32];                 // rope cos table
__device__ float g_rs[TT*32];                 // rope sin table

// k-permutation within 8-blocks: thread tg's pair (tg, tg+4) -> (2tg, 2tg+1)
__host__ __device__ __forceinline__ int kperm8(int j) {
    return ((j & 3) << 1) | (j >> 2);
}

// ---------------------------------------------------------------------------
// Helpers (legacy mma.sync tf32; tcgen05 needs the sm_103a feature target
// which this harness does not emit).
// ---------------------------------------------------------------------------
__device__ __forceinline__ uint32_t smem_u32(const void* p) {
    uint32_t a;
    asm("{ .reg .u64 t; cvta.to.shared.u64 t, %1; cvt.u32.u64 %0, t; }"
        : "=r"(a) : "l"(p));
    return a;
}
__device__ __forceinline__ uint32_t cvt_tf32(float f) {
    uint32_t u;
    asm("cvt.rna.tf32.f32 %0, %1;" : "=r"(u) : "f"(f));
    return u;
}
__device__ __forceinline__ float rnd_tf32(float f) {
    return __uint_as_float(cvt_tf32(f));
}
#define CP16(sa, gp) \
    asm volatile("cp.async.cg.shared.global [%0], [%1], 16;" :: "r"(sa), "l"(gp))
#define CP_COMMIT() asm volatile("cp.async.commit_group;" ::: "memory")
#define CP_WAIT1()  asm volatile("cp.async.wait_group 1;" ::: "memory")
#define CP_WAIT0()  asm volatile("cp.async.wait_group 0;" ::: "memory")

__device__ __forceinline__ void mma_tf32(float* c, const uint32_t* a,
                                         const uint32_t* b) {
    asm volatile(
        "mma.sync.aligned.m16n8k8.row.col.f32.tf32.tf32.f32 "
        "{%0,%1,%2,%3}, {%4,%5,%6,%7}, {%8,%9}, {%0,%1,%2,%3};"
        : "+f"(c[0]), "+f"(c[1]), "+f"(c[2]), "+f"(c[3])
        : "r"(a[0]), "r"(a[1]), "r"(a[2]), "r"(a[3]), "r"(b[0]), "r"(b[1]));
}

// ---------------------------------------------------------------------------
// Round x to tf32 + permute k within 8-blocks.
// ---------------------------------------------------------------------------
__global__ void round_x(const float* __restrict__ x)
{
    const int i = blockIdx.x * blockDim.x + threadIdx.x;   // 512K 8-blocks
    float4 a = ((const float4*)x)[2 * i];
    float4 b = ((const float4*)x)[2 * i + 1];
    float4 o0 = make_float4(rnd_tf32(a.x), rnd_tf32(b.x), rnd_tf32(a.y), rnd_tf32(b.y));
    float4 o1 = make_float4(rnd_tf32(a.z), rnd_tf32(b.z), rnd_tf32(a.w), rnd_tf32(b.w));
    ((float4*)g_xr)[2 * i] = o0;
    ((float4*)g_xr)[2 * i + 1] = o1;
}

// ---------------------------------------------------------------------------
// Weight transpose + round + k-permute: src [1024][C] -> dst [C][1024']
// ---------------------------------------------------------------------------
__global__ void transpose_kernel(const float* __restrict__ src,
                                 float* __restrict__ dst, int C)
{
    __shared__ float t[32][33];
    const int c0 = blockIdx.x * 32, r0 = blockIdx.y * 32;
    const int tx = threadIdx.x;
    for (int i = threadIdx.y; i < 32; i += 8)
        t[i][tx] = src[(size_t)(r0 + i) * C + c0 + tx];
    __syncthreads();
    const int kp = (tx & 24) | kperm8(tx & 7);
    for (int i = threadIdx.y; i < 32; i += 8)
        dst[(size_t)(c0 + i) * 1024 + r0 + kp] = rnd_tf32(t[tx][i]);
}

// ---------------------------------------------------------------------------
// mma.sync tf32 GEMM, CTA 128x128, BK=32, 8 warps, warp 64x32 (unchanged
// from R6 except V epilogue stores transposed [b,h,d,t], natural d).
// ---------------------------------------------------------------------------
#define PAD 40
#define ATILE (128 * PAD * 4)
#define STAGE (2 * ATILE)
#define GEMM_SMEM (2 * STAGE)   /* 81920 */

template <int MODE>
__global__ __launch_bounds__(256) void gemm_mma(
    const float* __restrict__ A, const float* __restrict__ Bt,
    const float* __restrict__ bias, float* __restrict__ out)
{
    extern __shared__ char smem[];
    const uint32_t sb = smem_u32(smem);
    const int tid = threadIdx.x;
    const int wid = tid >> 5;
    const int lane = tid & 31;
    const int gid = lane >> 2;
    const int tg = lane & 3;
    const int mb = (wid >> 2) * 64;
    const int nb = (wid & 3) * 32;
    const int m0 = blockIdx.y * 128;
    const int n0 = blockIdx.x * 128;

    float acc[4][4][4];
#pragma unroll
    for (int mf = 0; mf < 4; mf++)
#pragma unroll
        for (int nf = 0; nf < 4; nf++)
#pragma unroll
            for (int i = 0; i < 4; i++) acc[mf][nf][i] = 0.f;

    auto issue_tile = [&](int c) {
        const int p = c & 1;
        const int k0 = c * 32;
        const uint32_t aBase = sb + p * STAGE;
        const uint32_t bBase = aBase + ATILE;
#pragma unroll
        for (int i = 0; i < 4; i++) {
            const int e = tid + 256 * i;
            const int rr = e >> 3, q = e & 7;
            const float* gp;
            if (MODE == 0) {
                gp = &A[(size_t)(m0 + rr) * 1024 + k0 + q * 4];
            } else {
                const int m = m0 + rr, b = m >> 11, t = m & (TT - 1);
                const int kk = k0 + q * 4, h = kk >> 6, d = kk & 63;
                gp = &g_y[(((size_t)b * HH + h) * TT + t) * DHH + d];
            }
            CP16(aBase + (uint32_t)(rr * PAD + q * 4) * 4, gp);
        }
#pragma unroll
        for (int i = 0; i < 4; i++) {
            const int e = tid + 256 * i;
            const int rr = e >> 3, q = e & 7;
            const float* gp = &Bt[(size_t)(n0 + rr) * 1024 + k0 + q * 4];
            CP16(bBase + (uint32_t)(rr * PAD + q * 4) * 4, gp);
        }
        CP_COMMIT();
    };

    issue_tile(0);
    for (int c = 0; c < 32; c++) {
        if (c + 1 < 32) { issue_tile(c + 1); CP_WAIT1(); }
        else            { CP_WAIT0(); }
        __syncthreads();

        const int p = c & 1;
        const uint32_t* As = (const uint32_t*)(smem + p * STAGE);
        const uint32_t* Bs = (const uint32_t*)(smem + p * STAGE + ATILE);
#pragma unroll
        for (int ks = 0; ks < 4; ks++) {
            const int kk = ks * 8 + 2 * tg;
            uint32_t af[4][4], bf[4][2];
#pragma unroll
            for (int mf = 0; mf < 4; mf++) {
                const uint32_t* ap = As + (mb + mf * 16 + gid) * PAD + kk;
                uint2 lo = *(const uint2*)ap;
                uint2 hi = *(const uint2*)(ap + 8 * PAD);
                af[mf][0] = lo.x; af[mf][2] = lo.y;
                af[mf][1] = hi.x; af[mf][3] = hi.y;
            }
#pragma unroll
            for (int nf = 0; nf < 4; nf++) {
                const uint32_t* bp = Bs + (nb + nf * 8 + gid) * PAD + kk;
                uint2 v = *(const uint2*)bp;
                bf[nf][0] = v.x; bf[nf][1] = v.y;
            }
#pragma unroll
            for (int mf = 0; mf < 4; mf++)
#pragma unroll
                for (int nf = 0; nf < 4; nf++)
                    mma_tf32(acc[mf][nf], af[mf], bf[nf]);
        }
        __syncthreads();
    }

#pragma unroll
    for (int mf = 0; mf < 4; mf++) {
        const int r0 = m0 + mb + mf * 16 + gid;
#pragma unroll
        for (int nf = 0; nf < 4; nf++) {
            const int n = n0 + nb + nf * 8 + tg * 2;
            const float bx = bias[n], by = bias[n + 1];
            float2 v0 = make_float2(acc[mf][nf][0] + bx, acc[mf][nf][1] + by);
            float2 v1 = make_float2(acc[mf][nf][2] + bx, acc[mf][nf][3] + by);
            if (MODE == 0) {
                const int which = n >> 10;
                const int rr = n & 1023;
                const int h = rr >> 6, d = rr & 63;
                const int b0i = r0 >> 11, t0i = r0 & (TT - 1);
                const int m1 = r0 + 8;
                const int b1i = m1 >> 11, t1i = m1 & (TT - 1);
                if (which == 2) {
                    // V: rounded, transposed [b,h,d,t], natural d
                    const size_t vb0 = ((size_t)b0i * HH + h) * DHH;
                    const size_t vb1 = ((size_t)b1i * HH + h) * DHH;
                    g_v[(vb0 + d    ) * TT + t0i] = rnd_tf32(v0.x);
                    g_v[(vb0 + d + 1) * TT + t0i] = rnd_tf32(v0.y);
                    g_v[(vb1 + d    ) * TT + t1i] = rnd_tf32(v1.x);
                    g_v[(vb1 + d + 1) * TT + t1i] = rnd_tf32(v1.y);
                } else {
                    float* dst = (which == 0) ? g_q : g_k;
                    *(float2*)&dst[(((size_t)b0i * HH + h) * TT + t0i) * DHH + d] = v0;
                    *(float2*)&dst[(((size_t)b1i * HH + h) * TT + t1i) * DHH + d] = v1;
                }
            } else {
                *(float2*)&out[(size_t)r0 * DIMM + n] = v0;
                *(float2*)&out[(size_t)(r0 + 8) * DIMM + n] = v1;
            }
        }
    }
}

// ---------------------------------------------------------------------------
// RoPE: table build (fp64 once) + apply (writes q,k d-permuted; k rounded).
// ---------------------------------------------------------------------------
__global__ void build_rope()
{
    const int idx = blockIdx.x * blockDim.x + threadIdx.x;   // 65536
    const int d = idx & 31, t = idx >> 5;
    const float invf = (float)exp(-(double)d * (log(10000.0) / 32.0));
    const float ang = (float)t * invf;
    double sd, cd;
    sincos((double)ang, &sd, &cd);
    g_rc[t * 32 + d] = (float)cd;
    g_rs[t * 32 + d] = (float)sd;
}

__global__ void rope_apply()
{
    const int idx = blockIdx.x * blockDim.x + threadIdx.x;   // 2^21
    const int d  = idx & 31;
    const int t  = (idx >> 5) & (TT - 1);
    const int bh = idx >> 16;
    const float cf = g_rc[t * 32 + d];
    const float sf = g_rs[t * 32 + d];
    const int dp = (d & 24) | kperm8(d & 7);

    const size_t base = ((size_t)bh * TT + t) * DHH;
    const float qa = g_q[base + d], qb = g_q[base + 32 + d];
    const float ka = g_k[base + d], kb = g_k[base + 32 + d];
    g_q[base + dp]      = qa * cf - qb * sf;
    g_q[base + 32 + dp] = qa * sf + qb * cf;
    g_k[base + dp]      = rnd_tf32(ka * cf - kb * sf);
    g_k[base + 32 + dp] = rnd_tf32(ka * sf + kb * cf);
}

// ---------------------------------------------------------------------------
// Flash attention, mma.sync tf32, cp.async double-buffered K/V.
// S C-fragment reused directly as PV A-fragment (a = {c0,c2,c1,c3});
// V stored transposed [d][key] natural order -> B-frag pair (2tg,2tg+1)
// is one LDS.64. No P staging, no extra syncs. O written with explicit
// kperm8 so y matches gemm<1>'s pre-permuted A convention.
// ---------------------------------------------------------------------------
#define QPAD 72
#define VPAD 72
#define OFF_QH 0
#define OFF_QL (128*QPAD)
#define OFF_KS (2*128*QPAD)
#define OFF_VS (OFF_KS + 2*64*QPAD)
#define ATTN_SMEM ((OFF_VS + 2*64*VPAD) * 4)   /* 147456 */

__global__ __launch_bounds__(256) void attn_mma()
{
    extern __shared__ float sm[];
    uint32_t* Qh = (uint32_t*)sm + OFF_QH;
    uint32_t* Ql = (uint32_t*)sm + OFF_QL;
    const uint32_t sb = smem_u32(sm);

    const int qt = gridDim.x - 1 - blockIdx.x;   // heavy tiles first
    const int bh = blockIdx.y;
    const int tid = threadIdx.x;
    const int wid = tid >> 5;
    const int lane = tid & 31;
    const int gid = lane >> 2;
    const int tg = lane & 3;
    const int q0 = qt * 128;
    const int wrow = wid * 16;

    const float* Qg = g_q + ((size_t)bh * TT + q0) * DHH;
    const float* Kg = g_k + (size_t)bh * TT * DHH;
    const float* Vg = g_v + (size_t)bh * DHH * TT;   // [d][t]

    // Load Q (d-permuted in gmem), fold 1/8 scale, split hi/lo
#pragma unroll
    for (int i = 0; i < 8; i++) {
        const int e = tid + 256 * i;
        const int r = e >> 4, c = (e & 15) * 4;
        float4 v = *(const float4*)&Qg[r * DHH + c];
        float a[4] = {v.x * 0.125f, v.y * 0.125f, v.z * 0.125f, v.w * 0.125f};
#pragma unroll
        for (int j = 0; j < 4; j++) {
            const uint32_t hi = cvt_tf32(a[j]);
            Qh[r * QPAD + c + j] = hi;
            Ql[r * QPAD + c + j] = cvt_tf32(a[j] - __uint_as_float(hi));
        }
    }

    float oacc[8][4];
#pragma unroll
    for (int nf = 0; nf < 8; nf++)
#pragma unroll
        for (int i = 0; i < 4; i++) oacc[nf][i] = 0.f;
    float m0v = -INFINITY, m1v = -INFINITY, l0 = 0.f, l1 = 0.f;

    const int r0g = q0 + wrow + gid;
    const int r1g = r0g + 8;
    const int nkt = 2 * qt + 2;

    auto issue = [&](int kt) {
        const int st = kt & 1;
        const uint32_t kb = sb + (OFF_KS + st * 64 * QPAD) * 4;
        const uint32_t vb = sb + (OFF_VS + st * 64 * VPAD) * 4;
#pragma unroll
        for (int i = 0; i < 4; i++) {
            const int e = tid + 256 * i;
            const int r = e >> 4, c = (e & 15) * 4;
            CP16(kb + (uint32_t)(r * QPAD + c) * 4,
                 &Kg[(size_t)(kt * 64 + r) * DHH + c]);
            // V: row r = head-dim d, cols = keys
            CP16(vb + (uint32_t)(r * VPAD + c) * 4,
                 &Vg[(size_t)r * TT + kt * 64 + c]);
        }
        CP_COMMIT();
    };

    issue(0);
    for (int kt = 0; kt < nkt; kt++) {
        if (kt + 1 < nkt) { issue(kt + 1); CP_WAIT1(); }
        else              { CP_WAIT0(); }
        __syncthreads();

        if (kt * 64 <= q0 + wrow + 15) {
            const int st = kt & 1;
            const uint32_t* Ks = (const uint32_t*)sm + OFF_KS + st * 64 * QPAD;
            const uint32_t* Vs = (const uint32_t*)sm + OFF_VS + st * 64 * VPAD;

            // ---- S = Q K^T (hi + lo), paired LDS.64 frags ----
            float sacc[8][4];
#pragma unroll
            for (int nf = 0; nf < 8; nf++)
#pragma unroll
                for (int i = 0; i < 4; i++) sacc[nf][i] = 0.f;

#pragma unroll
            for (int ks = 0; ks < 8; ks++) {
                const int kk = ks * 8 + 2 * tg;
                const uint32_t* aph = Qh + (wrow + gid) * QPAD + kk;
                const uint32_t* apl = Ql + (wrow + gid) * QPAD + kk;
                uint2 h0 = *(const uint2*)aph;
                uint2 h1 = *(const uint2*)(aph + 8 * QPAD);
                uint2 l0v = *(const uint2*)apl;
                uint2 l1v = *(const uint2*)(apl + 8 * QPAD);
                uint32_t ah[4] = {h0.x, h1.x, h0.y, h1.y};
                uint32_t al[4] = {l0v.x, l1v.x, l0v.y, l1v.y};
#pragma unroll
                for (int nf = 0; nf < 8; nf++) {
                    uint2 bv = *(const uint2*)(Ks + (nf * 8 + gid) * QPAD + kk);
                    uint32_t bf[2] = {bv.x, bv.y};
                    mma_tf32(sacc[nf], ah, bf);
                    mma_tf32(sacc[nf], al, bf);
                }
            }

            // ---- causal mask ----
            if (kt >= 2 * qt) {
#pragma unroll
                for (int nf = 0; nf < 8; nf++) {
                    const int cb = kt * 64 + nf * 8 + 2 * tg;
                    if (cb     > r0g) sacc[nf][0] = -INFINITY;
                    if (cb + 1 > r0g) sacc[nf][1] = -INFINITY;
                    if (cb     > r1g) sacc[nf][2] = -INFINITY;
                    if (cb + 1 > r1g) sacc[nf][3] = -INFINITY;
                }
            }

            // ---- online softmax ----
            float mx0 = -INFINITY, mx1 = -INFINITY;
#pragma unroll
            for (int nf = 0; nf < 8; nf++) {
                mx0 = fmaxf(mx0, fmaxf(sacc[nf][0], sacc[nf][1]));
                mx1 = fmaxf(mx1, fmaxf(sacc[nf][2], sacc[nf][3]));
            }
            mx0 = fmaxf(mx0, __shfl_xor_sync(0xffffffffu, mx0, 1));
            mx0 = fmaxf(mx0, __shfl_xor_sync(0xffffffffu, mx0, 2));
            mx1 = fmaxf(mx1, __shfl_xor_sync(0xffffffffu, mx1, 1));
            mx1 = fmaxf(mx1, __shfl_xor_sync(0xffffffffu, mx1, 2));
            const float mn0 = fmaxf(m0v, mx0), mn1 = fmaxf(m1v, mx1);
            const float c0 = __expf(m0v - mn0), c1 = __expf(m1v - mn1);

            float rs0 = 0.f, rs1 = 0.f;
#pragma unroll
            for (int nf = 0; nf < 8; nf++) {
                sacc[nf][0] = __expf(sacc[nf][0] - mn0);
                sacc[nf][1] = __expf(sacc[nf][1] - mn0);
                sacc[nf][2] = __expf(sacc[nf][2] - mn1);
                sacc[nf][3] = __expf(sacc[nf][3] - mn1);
                rs0 += sacc[nf][0] + sacc[nf][1];
                rs1 += sacc[nf][2] + sacc[nf][3];
            }
            rs0 += __shfl_xor_sync(0xffffffffu, rs0, 1);
            rs0 += __shfl_xor_sync(0xffffffffu, rs0, 2);
            rs1 += __shfl_xor_sync(0xffffffffu, rs1, 1);
            rs1 += __shfl_xor_sync(0xffffffffu, rs1, 2);
            l0 = l0 * c0 + rs0;
            l1 = l1 * c1 + rs1;
            m0v = mn0; m1v = mn1;
#pragma unroll
            for (int nf = 0; nf < 8; nf++) {
                oacc[nf][0] *= c0; oacc[nf][1] *= c0;
                oacc[nf][2] *= c1; oacc[nf][3] *= c1;
            }

            // ---- O += P V : C-frag reused as A-frag (a = {c0,c2,c1,c3});
            //      effective key order (2tg,2tg+1) matches Vt natural cols ----
#pragma unroll
            for (int ks = 0; ks < 8; ks++) {
                uint32_t af[4] = {cvt_tf32(sacc[ks][0]), cvt_tf32(sacc[ks][2]),
                                  cvt_tf32(sacc[ks][1]), cvt_tf32(sacc[ks][3])};
                const int kk = ks * 8 + 2 * tg;
#pragma unroll
                for (int nf = 0; nf < 8; nf++) {
                    uint2 bv = *(const uint2*)(Vs + (nf * 8 + gid) * VPAD + kk);
                    uint32_t bf[2] = {bv.x, bv.y};
                    mma_tf32(oacc[nf], af, bf);
                }
            }
        }
        __syncthreads();
    }

    // ---- write O: natural-d columns -> apply kperm8 for gemm<1> layout ----
    const float i0 = 1.f / l0, i1 = 1.f / l1;
    const int p0 = kperm8(2 * tg), p1 = kperm8(2 * tg + 1);
    float* Yg = g_y + ((size_t)bh * TT + q0) * DHH;
#pragma unroll
    for (int nf = 0; nf < 8; nf++) {
        float* y0 = &Yg[(wrow + gid) * DHH + nf * 8];
        float* y1 = &Yg[(wrow + gid + 8) * DHH + nf * 8];
        y0[p0] = rnd_tf32(oacc[nf][0] * i0);
        y0[p1] = rnd_tf32(oacc[nf][1] * i0);
        y1[p0] = rnd_tf32(oacc[nf][2] * i1);
        y1[p1] = rnd_tf32(oacc[nf][3] * i1);
    }
}

// ---------------------------------------------------------------------------
extern "C" void kernel_launch(void* const* d_in, const int* in_sizes, int n_in,
                              void* d_out, int out_size)
{
    (void)in_sizes; (void)n_in; (void)out_size;
    const float* x     = (const float*)d_in[0];
    const float* W_qkv = (const float*)d_in[2];
    const float* b_qkv = (const float*)d_in[3];
    const float* W_out = (const float*)d_in[4];
    const float* b_out = (const float*)d_in[5];
    float* out = (float*)d_out;

    cudaFuncSetAttribute(attn_mma,
                         cudaFuncAttributeMaxDynamicSharedMemorySize, ATTN_SMEM);
    cudaFuncSetAttribute(gemm_mma<0>,
                         cudaFuncAttributeMaxDynamicSharedMemorySize, GEMM_SMEM);
    cudaFuncSetAttribute(gemm_mma<1>,
                         cudaFuncAttributeMaxDynamicSharedMemorySize, GEMM_SMEM);

    float* wtq = nullptr; cudaGetSymbolAddress((void**)&wtq, g_wtq);
    float* wto = nullptr; cudaGetSymbolAddress((void**)&wto, g_wto);
    float* xr  = nullptr; cudaGetSymbolAddress((void**)&xr, g_xr);

    // 0) prep: rope table, rounded+permuted x, rounded+permuted weights^T
    build_rope<<<256, 256>>>();
    round_x<<<(M_TOT * DIMM / 8) / 256, 256>>>(x);
    transpose_kernel<<<dim3(3072 / 32, 1024 / 32), dim3(32, 8)>>>(W_qkv, wtq, 3072);
    transpose_kernel<<<dim3(1024 / 32, 1024 / 32), dim3(32, 8)>>>(W_out, wto, 1024);

    // 1) QKV projection (V written transposed [b,h,d,t])
    gemm_mma<0><<<dim3(3072 / 128, M_TOT / 128), 256, GEMM_SMEM>>>(xr, wtq, b_qkv, nullptr);

    // 2) RoPE (q,k d-permuted; k rounded)
    rope_apply<<<(BB * HH * TT * 32) / 256, 256>>>();

    // 3) causal flash attention
    attn_mma<<<dim3(TT / 128, BB * HH), 256, ATTN_SMEM>>>();

    // 4) output projection
    gemm_mma<1><<<dim3(DIMM / 128, M_TOT / 128), 256, GEMM_SMEM>>>(nullptr, wto, b_out, out);
}

// round 8
// speedup vs baseline: 4.0050x; 1.0851x over previous
#include <cuda_runtime.h>
#include <math.h>
#include <stdint.h>

#define BB 2
#define TT 2048
#define DIMM 1024
#define HH 16
#define DHH 64
#define M_TOT (BB*TT)        /* 4096 */

// Scratch (static device globals; allocation is forbidden)
__device__ float g_q[(size_t)BB*HH*TT*DHH];   // [b,h,t,d']  (d k-permuted)
__device__ float g_k[(size_t)BB*HH*TT*DHH];   // [b,h,t,d']  (d k-permuted)
__device__ float g_v[(size_t)BB*HH*TT*DHH];   // [b,h,d,t]   TRANSPOSED, natural d
__device__ float g_y[(size_t)BB*HH*TT*DHH];   // [b,h,t,d']  (d k-permuted)
__device__ float g_xr[(size_t)M_TOT*DIMM];    // x rounded+k-permuted
__device__ float g_wtq[(size_t)3072*1024];    // W_qkv^T [n][k'] rounded+perm
__device__ float g_wto[(size_t)1024*1024];    // W_out^T [n][k'] rounded+perm
__device__ float g_rc[TT*32];                 // rope cos table
__device__ float g_rs[TT*32];                 // rope sin table

// k-permutation within 8-blocks: thread tg's pair (tg, tg+4) -> (2tg, 2tg+1)
__host__ __device__ __forceinline__ int kperm8(int j) {
    return ((j & 3) << 1) | (j >> 2);
}

// ---------------------------------------------------------------------------
// Helpers (legacy mma.sync tf32; tcgen05 needs the sm_103a feature target
// which this harness does not emit).
// ---------------------------------------------------------------------------
__device__ __forceinline__ uint32_t smem_u32(const void* p) {
    uint32_t a;
    asm("{ .reg .u64 t; cvta.to.shared.u64 t, %1; cvt.u32.u64 %0, t; }"
        : "=r"(a) : "l"(p));
    return a;
}
__device__ __forceinline__ uint32_t cvt_tf32(float f) {
    uint32_t u;
    asm("cvt.rna.tf32.f32 %0, %1;" : "=r"(u) : "f"(f));
    return u;
}
__device__ __forceinline__ float rnd_tf32(float f) {
    return __uint_as_float(cvt_tf32(f));
}
#define CP16(sa, gp) \
    asm volatile("cp.async.cg.shared.global [%0], [%1], 16;" :: "r"(sa), "l"(gp))
#define CP_COMMIT() asm volatile("cp.async.commit_group;" ::: "memory")
#define CP_WAIT1()  asm volatile("cp.async.wait_group 1;" ::: "memory")
#define CP_WAIT0()  asm volatile("cp.async.wait_group 0;" ::: "memory")

__device__ __forceinline__ void mma_tf32(float* c, const uint32_t* a,
                                         const uint32_t* b) {
    asm volatile(
        "mma.sync.aligned.m16n8k8.row.col.f32.tf32.tf32.f32 "
        "{%0,%1,%2,%3}, {%4,%5,%6,%7}, {%8,%9}, {%0,%1,%2,%3};"
        : "+f"(c[0]), "+f"(c[1]), "+f"(c[2]), "+f"(c[3])
        : "r"(a[0]), "r"(a[1]), "r"(a[2]), "r"(a[3]), "r"(b[0]), "r"(b[1]));
}

// ---------------------------------------------------------------------------
// Round x to tf32 + permute k within 8-blocks.
// ---------------------------------------------------------------------------
__global__ void round_x(const float* __restrict__ x)
{
    const int i = blockIdx.x * blockDim.x + threadIdx.x;   // 512K 8-blocks
    float4 a = ((const float4*)x)[2 * i];
    float4 b = ((const float4*)x)[2 * i + 1];
    float4 o0 = make_float4(rnd_tf32(a.x), rnd_tf32(b.x), rnd_tf32(a.y), rnd_tf32(b.y));
    float4 o1 = make_float4(rnd_tf32(a.z), rnd_tf32(b.z), rnd_tf32(a.w), rnd_tf32(b.w));
    ((float4*)g_xr)[2 * i] = o0;
    ((float4*)g_xr)[2 * i + 1] = o1;
}

// ---------------------------------------------------------------------------
// Weight transpose + round + k-permute: src [1024][C] -> dst [C][1024']
// ---------------------------------------------------------------------------
__global__ void transpose_kernel(const float* __restrict__ src,
                                 float* __restrict__ dst, int C)
{
    __shared__ float t[32][33];
    const int c0 = blockIdx.x * 32, r0 = blockIdx.y * 32;
    const int tx = threadIdx.x;
    for (int i = threadIdx.y; i < 32; i += 8)
        t[i][tx] = src[(size_t)(r0 + i) * C + c0 + tx];
    __syncthreads();
    const int kp = (tx & 24) | kperm8(tx & 7);
    for (int i = threadIdx.y; i < 32; i += 8)
        dst[(size_t)(c0 + i) * 1024 + r0 + kp] = rnd_tf32(t[tx][i]);
}

// ---------------------------------------------------------------------------
// mma.sync tf32 GEMM, CTA 128x128, BK=32, 8 warps, warp 64x32 (unchanged;
// V epilogue stores transposed [b,h,d,t], natural d).
// ---------------------------------------------------------------------------
#define PAD 40
#define ATILE (128 * PAD * 4)
#define STAGE (2 * ATILE)
#define GEMM_SMEM (2 * STAGE)   /* 81920 */

template <int MODE>
__global__ __launch_bounds__(256) void gemm_mma(
    const float* __restrict__ A, const float* __restrict__ Bt,
    const float* __restrict__ bias, float* __restrict__ out)
{
    extern __shared__ char smem[];
    const uint32_t sb = smem_u32(smem);
    const int tid = threadIdx.x;
    const int wid = tid >> 5;
    const int lane = tid & 31;
    const int gid = lane >> 2;
    const int tg = lane & 3;
    const int mb = (wid >> 2) * 64;
    const int nb = (wid & 3) * 32;
    const int m0 = blockIdx.y * 128;
    const int n0 = blockIdx.x * 128;

    float acc[4][4][4];
#pragma unroll
    for (int mf = 0; mf < 4; mf++)
#pragma unroll
        for (int nf = 0; nf < 4; nf++)
#pragma unroll
            for (int i = 0; i < 4; i++) acc[mf][nf][i] = 0.f;

    auto issue_tile = [&](int c) {
        const int p = c & 1;
        const int k0 = c * 32;
        const uint32_t aBase = sb + p * STAGE;
        const uint32_t bBase = aBase + ATILE;
#pragma unroll
        for (int i = 0; i < 4; i++) {
            const int e = tid + 256 * i;
            const int rr = e >> 3, q = e & 7;
            const float* gp;
            if (MODE == 0) {
                gp = &A[(size_t)(m0 + rr) * 1024 + k0 + q * 4];
            } else {
                const int m = m0 + rr, b = m >> 11, t = m & (TT - 1);
                const int kk = k0 + q * 4, h = kk >> 6, d = kk & 63;
                gp = &g_y[(((size_t)b * HH + h) * TT + t) * DHH + d];
            }
            CP16(aBase + (uint32_t)(rr * PAD + q * 4) * 4, gp);
        }
#pragma unroll
        for (int i = 0; i < 4; i++) {
            const int e = tid + 256 * i;
            const int rr = e >> 3, q = e & 7;
            const float* gp = &Bt[(size_t)(n0 + rr) * 1024 + k0 + q * 4];
            CP16(bBase + (uint32_t)(rr * PAD + q * 4) * 4, gp);
        }
        CP_COMMIT();
    };

    issue_tile(0);
    for (int c = 0; c < 32; c++) {
        if (c + 1 < 32) { issue_tile(c + 1); CP_WAIT1(); }
        else            { CP_WAIT0(); }
        __syncthreads();

        const int p = c & 1;
        const uint32_t* As = (const uint32_t*)(smem + p * STAGE);
        const uint32_t* Bs = (const uint32_t*)(smem + p * STAGE + ATILE);
#pragma unroll
        for (int ks = 0; ks < 4; ks++) {
            const int kk = ks * 8 + 2 * tg;
            uint32_t af[4][4], bf[4][2];
#pragma unroll
            for (int mf = 0; mf < 4; mf++) {
                const uint32_t* ap = As + (mb + mf * 16 + gid) * PAD + kk;
                uint2 lo = *(const uint2*)ap;
                uint2 hi = *(const uint2*)(ap + 8 * PAD);
                af[mf][0] = lo.x; af[mf][2] = lo.y;
                af[mf][1] = hi.x; af[mf][3] = hi.y;
            }
#pragma unroll
            for (int nf = 0; nf < 4; nf++) {
                const uint32_t* bp = Bs + (nb + nf * 8 + gid) * PAD + kk;
                uint2 v = *(const uint2*)bp;
                bf[nf][0] = v.x; bf[nf][1] = v.y;
            }
#pragma unroll
            for (int mf = 0; mf < 4; mf++)
#pragma unroll
                for (int nf = 0; nf < 4; nf++)
                    mma_tf32(acc[mf][nf], af[mf], bf[nf]);
        }
        __syncthreads();
    }

#pragma unroll
    for (int mf = 0; mf < 4; mf++) {
        const int r0 = m0 + mb + mf * 16 + gid;
#pragma unroll
        for (int nf = 0; nf < 4; nf++) {
            const int n = n0 + nb + nf * 8 + tg * 2;
            const float bx = bias[n], by = bias[n + 1];
            float2 v0 = make_float2(acc[mf][nf][0] + bx, acc[mf][nf][1] + by);
            float2 v1 = make_float2(acc[mf][nf][2] + bx, acc[mf][nf][3] + by);
            if (MODE == 0) {
                const int which = n >> 10;
                const int rr = n & 1023;
                const int h = rr >> 6, d = rr & 63;
                const int b0i = r0 >> 11, t0i = r0 & (TT - 1);
                const int m1 = r0 + 8;
                const int b1i = m1 >> 11, t1i = m1 & (TT - 1);
                if (which == 2) {
                    // V: rounded, transposed [b,h,d,t], natural d
                    const size_t vb0 = ((size_t)b0i * HH + h) * DHH;
                    const size_t vb1 = ((size_t)b1i * HH + h) * DHH;
                    g_v[(vb0 + d    ) * TT + t0i] = rnd_tf32(v0.x);
                    g_v[(vb0 + d + 1) * TT + t0i] = rnd_tf32(v0.y);
                    g_v[(vb1 + d    ) * TT + t1i] = rnd_tf32(v1.x);
                    g_v[(vb1 + d + 1) * TT + t1i] = rnd_tf32(v1.y);
                } else {
                    float* dst = (which == 0) ? g_q : g_k;
                    *(float2*)&dst[(((size_t)b0i * HH + h) * TT + t0i) * DHH + d] = v0;
                    *(float2*)&dst[(((size_t)b1i * HH + h) * TT + t1i) * DHH + d] = v1;
                }
            } else {
                *(float2*)&out[(size_t)r0 * DIMM + n] = v0;
                *(float2*)&out[(size_t)(r0 + 8) * DIMM + n] = v1;
            }
        }
    }
}

// ---------------------------------------------------------------------------
// RoPE: table build (fp64 once) + apply (writes q,k d-permuted; k rounded).
// ---------------------------------------------------------------------------
__global__ void build_rope()
{
    const int idx = blockIdx.x * blockDim.x + threadIdx.x;   // 65536
    const int d = idx & 31, t = idx >> 5;
    const float invf = (float)exp(-(double)d * (log(10000.0) / 32.0));
    const float ang = (float)t * invf;
    double sd, cd;
    sincos((double)ang, &sd, &cd);
    g_rc[t * 32 + d] = (float)cd;
    g_rs[t * 32 + d] = (float)sd;
}

__global__ void rope_apply()
{
    const int idx = blockIdx.x * blockDim.x + threadIdx.x;   // 2^21
    const int d  = idx & 31;
    const int t  = (idx >> 5) & (TT - 1);
    const int bh = idx >> 16;
    const float cf = g_rc[t * 32 + d];
    const float sf = g_rs[t * 32 + d];
    const int dp = (d & 24) | kperm8(d & 7);

    const size_t base = ((size_t)bh * TT + t) * DHH;
    const float qa = g_q[base + d], qb = g_q[base + 32 + d];
    const float ka = g_k[base + d], kb = g_k[base + 32 + d];
    g_q[base + dp]      = qa * cf - qb * sf;
    g_q[base + 32 + dp] = qa * sf + qb * cf;
    g_k[base + dp]      = rnd_tf32(ka * cf - kb * sf);
    g_k[base + 32 + dp] = rnd_tf32(ka * sf + kb * cf);
}

// ---------------------------------------------------------------------------
// Flash attention, mma.sync tf32, cp.async double-buffered K/V.
// Single tf32 Q (no hi/lo split): S MMA count halved, Ql SMEM freed ->
// 110.6 KB -> 2 CTAs/SM (16 warps). S C-frag reused directly as PV A-frag;
// V transposed [d][key] natural order -> paired LDS.64 B-frags. O written
// with explicit kperm8 so y matches gemm<1>'s pre-permuted A convention.
// ---------------------------------------------------------------------------
#define QPAD 72
#define VPAD 72
#define OFF_QH 0
#define OFF_KS (128*QPAD)
#define OFF_VS (OFF_KS + 2*64*QPAD)
#define ATTN_SMEM ((OFF_VS + 2*64*VPAD) * 4)   /* 110592 */

__global__ __launch_bounds__(256, 2) void attn_mma()
{
    extern __shared__ float sm[];
    uint32_t* Qh = (uint32_t*)sm + OFF_QH;
    const uint32_t sb = smem_u32(sm);

    const int qt = gridDim.x - 1 - blockIdx.x;   // heavy tiles first
    const int bh = blockIdx.y;
    const int tid = threadIdx.x;
    const int wid = tid >> 5;
    const int lane = tid & 31;
    const int gid = lane >> 2;
    const int tg = lane & 3;
    const int q0 = qt * 128;
    const int wrow = wid * 16;

    const float* Qg = g_q + ((size_t)bh * TT + q0) * DHH;
    const float* Kg = g_k + (size_t)bh * TT * DHH;
    const float* Vg = g_v + (size_t)bh * DHH * TT;   // [d][t]

    // Load Q (d-permuted in gmem), fold 1/8 scale, single tf32 rounding
#pragma unroll
    for (int i = 0; i < 8; i++) {
        const int e = tid + 256 * i;
        const int r = e >> 4, c = (e & 15) * 4;
        float4 v = *(const float4*)&Qg[r * DHH + c];
        Qh[r * QPAD + c + 0] = cvt_tf32(v.x * 0.125f);
        Qh[r * QPAD + c + 1] = cvt_tf32(v.y * 0.125f);
        Qh[r * QPAD + c + 2] = cvt_tf32(v.z * 0.125f);
        Qh[r * QPAD + c + 3] = cvt_tf32(v.w * 0.125f);
    }

    float oacc[8][4];
#pragma unroll
    for (int nf = 0; nf < 8; nf++)
#pragma unroll
        for (int i = 0; i < 4; i++) oacc[nf][i] = 0.f;
    float m0v = -INFINITY, m1v = -INFINITY, l0 = 0.f, l1 = 0.f;

    const int r0g = q0 + wrow + gid;
    const int r1g = r0g + 8;
    const int nkt = 2 * qt + 2;

    auto issue = [&](int kt) {
        const int st = kt & 1;
        const uint32_t kb = sb + (OFF_KS + st * 64 * QPAD) * 4;
        const uint32_t vb = sb + (OFF_VS + st * 64 * VPAD) * 4;
#pragma unroll
        for (int i = 0; i < 4; i++) {
            const int e = tid + 256 * i;
            const int r = e >> 4, c = (e & 15) * 4;
            CP16(kb + (uint32_t)(r * QPAD + c) * 4,
                 &Kg[(size_t)(kt * 64 + r) * DHH + c]);
            // V: row r = head-dim d, cols = keys
            CP16(vb + (uint32_t)(r * VPAD + c) * 4,
                 &Vg[(size_t)r * TT + kt * 64 + c]);
        }
        CP_COMMIT();
    };

    issue(0);
    for (int kt = 0; kt < nkt; kt++) {
        if (kt + 1 < nkt) { issue(kt + 1); CP_WAIT1(); }
        else              { CP_WAIT0(); }
        __syncthreads();

        if (kt * 64 <= q0 + wrow + 15) {
            const int st = kt & 1;
            const uint32_t* Ks = (const uint32_t*)sm + OFF_KS + st * 64 * QPAD;
            const uint32_t* Vs = (const uint32_t*)sm + OFF_VS + st * 64 * VPAD;

            // ---- S = Q K^T (single tf32), paired LDS.64 frags ----
            float sacc[8][4];
#pragma unroll
            for (int nf = 0; nf < 8; nf++)
#pragma unroll
                for (int i = 0; i < 4; i++) sacc[nf][i] = 0.f;

#pragma unroll
            for (int ks = 0; ks < 8; ks++) {
                const int kk = ks * 8 + 2 * tg;
                const uint32_t* aph = Qh + (wrow + gid) * QPAD + kk;
                uint2 h0 = *(const uint2*)aph;
                uint2 h1 = *(const uint2*)(aph + 8 * QPAD);
                uint32_t ah[4] = {h0.x, h1.x, h0.y, h1.y};
#pragma unroll
                for (int nf = 0; nf < 8; nf++) {
                    uint2 bv = *(const uint2*)(Ks + (nf * 8 + gid) * QPAD + kk);
                    uint32_t bf[2] = {bv.x, bv.y};
                    mma_tf32(sacc[nf], ah, bf);
                }
            }

            // ---- causal mask ----
            if (kt >= 2 * qt) {
#pragma unroll
                for (int nf = 0; nf < 8; nf++) {
                    const int cb = kt * 64 + nf * 8 + 2 * tg;
                    if (cb     > r0g) sacc[nf][0] = -INFINITY;
                    if (cb + 1 > r0g) sacc[nf][1] = -INFINITY;
                    if (cb     > r1g) sacc[nf][2] = -INFINITY;
                    if (cb + 1 > r1g) sacc[nf][3] = -INFINITY;
                }
            }

            // ---- online softmax ----
            float mx0 = -INFINITY, mx1 = -INFINITY;
#pragma unroll
            for (int nf = 0; nf < 8; nf++) {
                mx0 = fmaxf(mx0, fmaxf(sacc[nf][0], sacc[nf][1]));
                mx1 = fmaxf(mx1, fmaxf(sacc[nf][2], sacc[nf][3]));
            }
            mx0 = fmaxf(mx0, __shfl_xor_sync(0xffffffffu, mx0, 1));
            mx0 = fmaxf(mx0, __shfl_xor_sync(0xffffffffu, mx0, 2));
            mx1 = fmaxf(mx1, __shfl_xor_sync(0xffffffffu, mx1, 1));
            mx1 = fmaxf(mx1, __shfl_xor_sync(0xffffffffu, mx1, 2));
            const float mn0 = fmaxf(m0v, mx0), mn1 = fmaxf(m1v, mx1);
            const float c0 = __expf(m0v - mn0), c1 = __expf(m1v - mn1);

            float rs0 = 0.f, rs1 = 0.f;
#pragma unroll
            for (int nf = 0; nf < 8; nf++) {
                sacc[nf][0] = __expf(sacc[nf][0] - mn0);
                sacc[nf][1] = __expf(sacc[nf][1] - mn0);
                sacc[nf][2] = __expf(sacc[nf][2] - mn1);
                sacc[nf][3] = __expf(sacc[nf][3] - mn1);
                rs0 += sacc[nf][0] + sacc[nf][1];
                rs1 += sacc[nf][2] + sacc[nf][3];
            }
            rs0 += __shfl_xor_sync(0xffffffffu, rs0, 1);
            rs0 += __shfl_xor_sync(0xffffffffu, rs0, 2);
            rs1 += __shfl_xor_sync(0xffffffffu, rs1, 1);
            rs1 += __shfl_xor_sync(0xffffffffu, rs1, 2);
            l0 = l0 * c0 + rs0;
            l1 = l1 * c1 + rs1;
            m0v = mn0; m1v = mn1;
#pragma unroll
            for (int nf = 0; nf < 8; nf++) {
                oacc[nf][0] *= c0; oacc[nf][1] *= c0;
                oacc[nf][2] *= c1; oacc[nf][3] *= c1;
            }

            // ---- O += P V : C-frag reused as A-frag (a = {c0,c2,c1,c3});
            //      effective key order (2tg,2tg+1) matches Vt natural cols ----
#pragma unroll
            for (int ks = 0; ks < 8; ks++) {
                uint32_t af[4] = {cvt_tf32(sacc[ks][0]), cvt_tf32(sacc[ks][2]),
                                  cvt_tf32(sacc[ks][1]), cvt_tf32(sacc[ks][3])};
                const int kk = ks * 8 + 2 * tg;
#pragma unroll
                for (int nf = 0; nf < 8; nf++) {
                    uint2 bv = *(const uint2*)(Vs + (nf * 8 + gid) * VPAD + kk);
                    uint32_t bf[2] = {bv.x, bv.y};
                    mma_tf32(oacc[nf], af, bf);
                }
            }
        }
        __syncthreads();
    }

    // ---- write O: natural-d columns -> apply kperm8 for gemm<1> layout ----
    const float i0 = 1.f / l0, i1 = 1.f / l1;
    const int p0 = kperm8(2 * tg), p1 = kperm8(2 * tg + 1);
    float* Yg = g_y + ((size_t)bh * TT + q0) * DHH;
#pragma unroll
    for (int nf = 0; nf < 8; nf++) {
        float* y0 = &Yg[(wrow + gid) * DHH + nf * 8];
        float* y1 = &Yg[(wrow + gid + 8) * DHH + nf * 8];
        y0[p0] = rnd_tf32(oacc[nf][0] * i0);
        y0[p1] = rnd_tf32(oacc[nf][1] * i0);
        y1[p0] = rnd_tf32(oacc[nf][2] * i1);
        y1[p1] = rnd_tf32(oacc[nf][3] * i1);
    }
}

// ---------------------------------------------------------------------------
extern "C" void kernel_launch(void* const* d_in, const int* in_sizes, int n_in,
                              void* d_out, int out_size)
{
    (void)in_sizes; (void)n_in; (void)out_size;
    const float* x     = (const float*)d_in[0];
    const float* W_qkv = (const float*)d_in[2];
    const float* b_qkv = (const float*)d_in[3];
    const float* W_out = (const float*)d_in[4];
    const float* b_out = (const float*)d_in[5];
    float* out = (float*)d_out;

    cudaFuncSetAttribute(attn_mma,
                         cudaFuncAttributeMaxDynamicSharedMemorySize, ATTN_SMEM);
    cudaFuncSetAttribute(gemm_mma<0>,
                         cudaFuncAttributeMaxDynamicSharedMemorySize, GEMM_SMEM);
    cudaFuncSetAttribute(gemm_mma<1>,
                         cudaFuncAttributeMaxDynamicSharedMemorySize, GEMM_SMEM);

    float* wtq = nullptr; cudaGetSymbolAddress((void**)&wtq, g_wtq);
    float* wto = nullptr; cudaGetSymbolAddress((void**)&wto, g_wto);
    float* xr  = nullptr; cudaGetSymbolAddress((void**)&xr, g_xr);

    // 0) prep: rope table, rounded+permuted x, rounded+permuted weights^T
    build_rope<<<256, 256>>>();
    round_x<<<(M_TOT * DIMM / 8) / 256, 256>>>(x);
    transpose_kernel<<<dim3(3072 / 32, 1024 / 32), dim3(32, 8)>>>(W_qkv, wtq, 3072);
    transpose_kernel<<<dim3(1024 / 32, 1024 / 32), dim3(32, 8)>>>(W_out, wto, 1024);

    // 1) QKV projection (V written transposed [b,h,d,t])
    gemm_mma<0><<<dim3(3072 / 128, M_TOT / 128), 256, GEMM_SMEM>>>(xr, wtq, b_qkv, nullptr);

    // 2) RoPE (q,k d-permuted; k rounded)
    rope_apply<<<(BB * HH * TT * 32) / 256, 256>>>();

    // 3) causal flash attention
    attn_mma<<<dim3(TT / 128, BB * HH), 256, ATTN_SMEM>>>();

    // 4) output projection
    gemm_mma<1><<<dim3(DIMM / 128, M_TOT / 128), 256, GEMM_SMEM>>>(nullptr, wto, b_out, out);
}